// round 12
// baseline (speedup 1.0000x reference)
#include <cuda_runtime.h>
#include <cuda_bf16.h>
#include <cstdint>
#include <math.h>

// Problem constants (match reference)
#define NNODES 50000
#define NEDGES 400000
#define NGRAPH 64
#define NHEAD  4
#define F1 256
#define F2 128
#define NB 196   // ceil(NNODES/256)

// ---------------------------------------------------------------------------
// Device scratch
// ---------------------------------------------------------------------------
__device__ float g_h[NNODES * F1];
__device__ float g_out0[NNODES * F1];
__device__ float g_out1[NNODES * F1];
__device__ float g_comb[NNODES * F1];       // combined layer-1 output (tf32)
__device__ float g_x[NNODES * 128];         // tf32-rounded input features
__device__ float g_wa[128 * 256];           // rounded proj1_w [K][F]
__device__ float g_wb[256 * 256];           // rounded klin1_w
__device__ float g_wc[128 * 128];           // rounded klin2_w
__device__ float g_wd[256 * 128];           // rounded proj2_w
__device__ float g_s[2 * NNODES * NHEAD];
__device__ float g_dd[2 * NNODES * NHEAD];
__device__ float g_wsum[2 * F1 + 2 * F2];   // layer1 @0, layer2 @512
__device__ float g_attn[2];
__device__ float g_pool[NGRAPH * F2];
__device__ float g_cnt[NGRAPH];
// CSR (by dst), 2 relations; adjacency stores SRC node ids directly
__device__ int g_deg[2 * NNODES];
__device__ int g_rowptr[2 * NNODES];
__device__ int g_cursor[2 * NNODES];
__device__ int g_adj[2 * NEDGES];
__device__ int g_partials[2 * NB];

// ---------------------------------------------------------------------------
// Helpers
// ---------------------------------------------------------------------------
__device__ __forceinline__ unsigned to_tf32_bits(float x) {
    unsigned r;
    asm("cvt.rna.tf32.f32 %0, %1;" : "=r"(r) : "f"(x));
    return r;
}
__device__ __forceinline__ float to_tf32(float x) {
    return __uint_as_float(to_tf32_bits(x));
}
__device__ __forceinline__ float tanh_fast(float x) {
    float y;
    asm("tanh.approx.f32 %0, %1;" : "=f"(y) : "f"(x));
    return y;
}

__device__ __forceinline__ void mma_tf32(float c[4],
                                         const unsigned a[4],
                                         const unsigned b[2]) {
    asm volatile(
        "mma.sync.aligned.m16n8k8.row.col.f32.tf32.tf32.f32 "
        "{%0,%1,%2,%3}, {%4,%5,%6,%7}, {%8,%9}, {%0,%1,%2,%3};"
        : "+f"(c[0]), "+f"(c[1]), "+f"(c[2]), "+f"(c[3])
        : "r"(a[0]), "r"(a[1]), "r"(a[2]), "r"(a[3]),
          "r"(b[0]), "r"(b[1]));
}

__device__ __forceinline__ void cp_async16(uint32_t s, const void* g, bool v) {
    int sz = v ? 16 : 0;
    asm volatile("cp.async.ca.shared.global [%0], [%1], 16, %2;"
                 :: "r"(s), "l"(g), "r"(sz));
}
__device__ __forceinline__ void cp_commit() {
    asm volatile("cp.async.commit_group;" ::: "memory");
}
template<int N>
__device__ __forceinline__ void cp_wait() {
    asm volatile("cp.async.wait_group %0;" :: "n"(N) : "memory");
}

__global__ void round_copy(const float* __restrict__ in,
                           float* __restrict__ out, long n) {
    long i = (long)blockIdx.x * blockDim.x + threadIdx.x;
    if (i < n) out[i] = to_tf32(in[i]);
}

// ---------------------------------------------------------------------------
// CSR build kernels
// ---------------------------------------------------------------------------
__global__ void prep_zero(int* __restrict__ deg, float* __restrict__ pool,
                          float* __restrict__ cnt, float* __restrict__ wsum) {
    int i = blockIdx.x * 256 + threadIdx.x;
    if (i < 2 * NNODES) deg[i] = 0;
    if (i < NGRAPH * F2) pool[i] = 0.f;
    if (i < NGRAPH) cnt[i] = 0.f;
    if (i < 2 * F1 + 2 * F2) wsum[i] = 0.f;
}

__global__ void hist_kernel(const int* __restrict__ ei0,
                            const int* __restrict__ ei1,
                            int* __restrict__ deg) {
    int r = blockIdx.y;
    const int* dst = (r == 0 ? ei0 : ei1) + NEDGES;
    int e = blockIdx.x * 256 + threadIdx.x;
    if (e < NEDGES) atomicAdd(&deg[r * NNODES + dst[e]], 1);
}

__global__ void scan1_kernel(const int* __restrict__ deg,
                             int* __restrict__ rowptr,
                             int* __restrict__ partials) {
    int r = blockIdx.y, b = blockIdx.x, t = threadIdx.x;
    int i = b * 256 + t;
    __shared__ int sh[256];
    int v = (i < NNODES) ? deg[r * NNODES + i] : 0;
    sh[t] = v;
    __syncthreads();
    for (int off = 1; off < 256; off <<= 1) {
        int x = (t >= off) ? sh[t - off] : 0;
        __syncthreads();
        sh[t] += x;
        __syncthreads();
    }
    if (i < NNODES) rowptr[r * NNODES + i] = sh[t] - v;  // exclusive
    if (t == 255) partials[r * NB + b] = sh[t];
}

__global__ void scan2_kernel(int* __restrict__ partials) {
    int r = blockIdx.x, t = threadIdx.x;
    __shared__ int sh[256];
    int v = (t < NB) ? partials[r * NB + t] : 0;
    sh[t] = v;
    __syncthreads();
    for (int off = 1; off < 256; off <<= 1) {
        int x = (t >= off) ? sh[t - off] : 0;
        __syncthreads();
        sh[t] += x;
        __syncthreads();
    }
    if (t < NB) partials[r * NB + t] = sh[t] - v;  // exclusive
}

__global__ void scan3_kernel(int* __restrict__ rowptr,
                             const int* __restrict__ partials,
                             int* __restrict__ cursor) {
    int r = blockIdx.y;
    int i = blockIdx.x * 256 + threadIdx.x;
    if (i < NNODES) {
        int v = rowptr[r * NNODES + i] + partials[r * NB + blockIdx.x];
        rowptr[r * NNODES + i] = v;
        cursor[r * NNODES + i] = v;
    }
}

__global__ void fillpos_kernel(const int* __restrict__ ei0,
                               const int* __restrict__ ei1,
                               int* __restrict__ cursor,
                               int* __restrict__ adj) {
    int r = blockIdx.y;
    const int* ei = (r == 0 ? ei0 : ei1);
    int e = blockIdx.x * 256 + threadIdx.x;
    if (e < NEDGES) {
        int pos = atomicAdd(&cursor[r * NNODES + ei[NEDGES + e]], 1);
        adj[r * NEDGES + pos] = ei[e];
    }
}

// ---------------------------------------------------------------------------
// Fast TF32 GEMM (cp.async 4-stage) — measured ~44us on proj1 (CONTROL).
// A pre-rounded [M][K]; W pre-rounded [K][F]. C[M,F] = A @ W (+bias)
// mode 0: C = acc + bias; mode 1: colsum += sum_m tanh(acc + bias)
// grid.z selects A0/A1 (batched klin GEMMs); colsum offset = z*F.
// ---------------------------------------------------------------------------
#define GBM 128
#define GBN 128
#define FBK 8
#define FA_STRIDE 12
#define FB_STRIDE 136
#define FSTAGES 4

__global__ __launch_bounds__(256) void mma_gemm_async(
    const float* __restrict__ A0, const float* __restrict__ A1,
    const float* __restrict__ W,
    const float* __restrict__ bias, float* __restrict__ C,
    int M, int K, int F, int mode, float* __restrict__ colsum)
{
    __shared__ float As[FSTAGES][GBM][FA_STRIDE];   // 24576 B
    __shared__ float Bs[FSTAGES][FBK][FB_STRIDE];   // 17408 B

    const float* __restrict__ A = (blockIdx.z == 0) ? A0 : A1;
    float* cs = (mode == 1) ? colsum + blockIdx.z * F : nullptr;

    const int tid  = threadIdx.x;
    const int lane = tid & 31;
    const int warp = tid >> 5;
    const int wm   = warp & 1;
    const int wn   = warp >> 1;
    const int gid  = lane >> 2;
    const int tig  = lane & 3;

    const int rowBase = blockIdx.y * GBM;
    const int colBase = blockIdx.x * GBN;

    const int a_r = tid >> 1;          // 0..127
    const int a_c = (tid & 1) * 4;     // 0 or 4
    const int b_r = tid >> 5;          // 0..7
    const int b_c = (tid & 31) * 4;    // 0..124
    const bool a_valid = (rowBase + a_r) < M;
    const uint32_t a_sbase = (uint32_t)__cvta_generic_to_shared(&As[0][a_r][a_c]);
    const uint32_t b_sbase = (uint32_t)__cvta_generic_to_shared(&Bs[0][b_r][b_c]);
    const size_t a_goff = (size_t)(rowBase + a_r) * K + a_c;
    const size_t b_goff = (size_t)b_r * F + colBase + b_c;
    const uint32_t a_stage_b = GBM * FA_STRIDE * 4;
    const uint32_t b_stage_b = FBK * FB_STRIDE * 4;

    float acc[4][4][4];
#pragma unroll
    for (int mt = 0; mt < 4; mt++)
#pragma unroll
        for (int nt = 0; nt < 4; nt++)
#pragma unroll
            for (int i = 0; i < 4; i++) acc[mt][nt][i] = 0.f;

    const int KT = K / FBK;

#define ISSUE(stage, kt_) do {                                              \
        cp_async16(a_sbase + (stage) * a_stage_b,                           \
                   A + a_goff + (size_t)(kt_) * FBK, a_valid);              \
        cp_async16(b_sbase + (stage) * b_stage_b,                           \
                   W + b_goff + (size_t)(kt_) * FBK * F, true);             \
        cp_commit();                                                        \
    } while (0)

    ISSUE(0, 0);
    ISSUE(1, 1);
    ISSUE(2, 2);

    for (int kt = 0; kt < KT; kt++) {
        const int rem = KT - kt - 1;
        if (rem >= 2)      cp_wait<2>();
        else if (rem == 1) cp_wait<1>();
        else               cp_wait<0>();
        __syncthreads();

        const int buf = kt & (FSTAGES - 1);
        unsigned afr[4][4], bfr[4][2];
#pragma unroll
        for (int mt = 0; mt < 4; mt++) {
            int r = wm * 64 + mt * 16 + gid;
            afr[mt][0] = __float_as_uint(As[buf][r][tig]);
            afr[mt][1] = __float_as_uint(As[buf][r + 8][tig]);
            afr[mt][2] = __float_as_uint(As[buf][r][tig + 4]);
            afr[mt][3] = __float_as_uint(As[buf][r + 8][tig + 4]);
        }
#pragma unroll
        for (int nt = 0; nt < 4; nt++) {
            int c = wn * 32 + nt * 8 + gid;
            bfr[nt][0] = __float_as_uint(Bs[buf][tig][c]);
            bfr[nt][1] = __float_as_uint(Bs[buf][tig + 4][c]);
        }
#pragma unroll
        for (int mt = 0; mt < 4; mt++)
#pragma unroll
            for (int nt = 0; nt < 4; nt++)
                mma_tf32(acc[mt][nt], afr[mt], bfr[nt]);

        if (kt + FSTAGES - 1 < KT)
            ISSUE((kt + FSTAGES - 1) & (FSTAGES - 1), kt + FSTAGES - 1);
    }
#undef ISSUE

    if (mode == 0) {
#pragma unroll
        for (int mt = 0; mt < 4; mt++) {
            int r0 = rowBase + wm * 64 + mt * 16 + gid;
            int r1 = r0 + 8;
#pragma unroll
            for (int nt = 0; nt < 4; nt++) {
                int gc = colBase + wn * 32 + nt * 8 + tig * 2;
                float b0 = bias[gc], b1 = bias[gc + 1];
                if (r0 < M) {
                    float2 v = make_float2(acc[mt][nt][0] + b0, acc[mt][nt][1] + b1);
                    *reinterpret_cast<float2*>(&C[(size_t)r0 * F + gc]) = v;
                }
                if (r1 < M) {
                    float2 v = make_float2(acc[mt][nt][2] + b0, acc[mt][nt][3] + b1);
                    *reinterpret_cast<float2*>(&C[(size_t)r1 * F + gc]) = v;
                }
            }
        }
    } else {
#pragma unroll
        for (int nt = 0; nt < 4; nt++) {
            int gc = colBase + wn * 32 + nt * 8 + tig * 2;
            float b0 = bias[gc], b1 = bias[gc + 1];
            float csA = 0.f, csB = 0.f;
#pragma unroll
            for (int mt = 0; mt < 4; mt++) {
                int r0 = rowBase + wm * 64 + mt * 16 + gid;
                int r1 = r0 + 8;
                if (r0 < M) {
                    csA += tanh_fast(acc[mt][nt][0] + b0);
                    csB += tanh_fast(acc[mt][nt][1] + b1);
                }
                if (r1 < M) {
                    csA += tanh_fast(acc[mt][nt][2] + b0);
                    csB += tanh_fast(acc[mt][nt][3] + b1);
                }
            }
            // reduce across gid (lanes with same tig share gc): xor 4,8,16
#pragma unroll
            for (int o = 4; o <= 16; o <<= 1) {
                csA += __shfl_xor_sync(0xffffffffu, csA, o);
                csB += __shfl_xor_sync(0xffffffffu, csB, o);
            }
            if (gid == 0) {
                atomicAdd(&cs[gc], csA);
                atomicAdd(&cs[gc + 1], csB);
            }
        }
    }
}

// ---------------------------------------------------------------------------
// Per-(node,head) attention scores, BOTH relations in one pass (h read once)
// ---------------------------------------------------------------------------
__global__ void node_scores_kernel(const float* __restrict__ h,
                                   const float* __restrict__ as0,
                                   const float* __restrict__ ad0,
                                   const float* __restrict__ as1,
                                   const float* __restrict__ ad1,
                                   float* __restrict__ s, float* __restrict__ d,
                                   int n, int F, int D)
{
    int idx = blockIdx.x * blockDim.x + threadIdx.x;
    if (idx >= n * NHEAD) return;
    int node = idx / NHEAD;
    int hh   = idx % NHEAD;
    const float4* hp4 = (const float4*)(h + (size_t)node * F + hh * D);
    const float4* a0 = (const float4*)(as0 + hh * D);
    const float4* b0 = (const float4*)(ad0 + hh * D);
    const float4* a1 = (const float4*)(as1 + hh * D);
    const float4* b1 = (const float4*)(ad1 + hh * D);
    float s0 = 0.f, d0 = 0.f, s1 = 0.f, d1 = 0.f;
    for (int i = 0; i < D / 4; i++) {
        float4 hv = hp4[i];
        float4 av = a0[i], bv = b0[i], cv = a1[i], dv = b1[i];
        s0 += hv.x * av.x + hv.y * av.y + hv.z * av.z + hv.w * av.w;
        d0 += hv.x * bv.x + hv.y * bv.y + hv.z * bv.z + hv.w * bv.w;
        s1 += hv.x * cv.x + hv.y * cv.y + hv.z * cv.z + hv.w * cv.w;
        d1 += hv.x * dv.x + hv.y * dv.y + hv.z * dv.z + hv.w * dv.w;
    }
    s[idx] = s0;               d[idx] = d0;
    s[n * NHEAD + idx] = s1;   d[n * NHEAD + idx] = d1;
}

// ---------------------------------------------------------------------------
// Gather-aggregate: warp per dst node, both relations (grid.y), float4 I/O.
// Pass 1 caches first-wave edge src + scores in regs; pass 2 shuffles them
// and processes FOUR edges per iteration (MLP=4 on row gathers).
// ---------------------------------------------------------------------------
template<int F, int D>
__global__ __launch_bounds__(256) void agg_kernel(
    const int* __restrict__ rowptr, const int* __restrict__ deg,
    const int* __restrict__ adjacency,
    const float* __restrict__ h, const float* __restrict__ s,
    const float* __restrict__ dvals,
    float* __restrict__ out0, float* __restrict__ out1, int n)
{
    const int r = blockIdx.y;
    float* __restrict__ out = r == 0 ? out0 : out1;
    const int* rp = rowptr + r * n;
    const int* dgp = deg + r * n;
    const int* __restrict__ adj = adjacency + r * NEDGES;
    const float4* __restrict__ sp4 =
        (const float4*)(s + (size_t)r * n * NHEAD);
    const float4* __restrict__ dp4 =
        (const float4*)(dvals + (size_t)r * n * NHEAD);

    int w = blockIdx.x * (blockDim.x >> 5) + (threadIdx.x >> 5);
    int lane = threadIdx.x & 31;
    if (w >= n) return;
    const int dg = dgp[w];
    const int st = rp[w];
    constexpr int C4 = F / 128;       // float4 per lane
    float4 acc4[C4];
#pragma unroll
    for (int c = 0; c < C4; c++) acc4[c] = make_float4(0.f, 0.f, 0.f, 0.f);
    float4 ddv = dp4[w];
    float dd[4] = {ddv.x, ddv.y, ddv.z, ddv.w};

    // pass 1: per-head max; cache first-wave (j = lane) src + scores
    int sr0 = 0;
    float vv[4] = {0.f, 0.f, 0.f, 0.f};
    float m[4] = {-1e30f, -1e30f, -1e30f, -1e30f};
    for (int j = lane; j < dg; j += 32) {
        int sr = adj[st + j];
        float4 sv = sp4[sr];
        float v[4];
        v[0] = sv.x + dd[0]; v[1] = sv.y + dd[1];
        v[2] = sv.z + dd[2]; v[3] = sv.w + dd[3];
#pragma unroll
        for (int t = 0; t < 4; t++) {
            v[t] = (v[t] >= 0.f) ? v[t] : 0.2f * v[t];
            m[t] = fmaxf(m[t], v[t]);
        }
        if (j == lane) {
            sr0 = sr;
#pragma unroll
            for (int t = 0; t < 4; t++) vv[t] = v[t];
        }
    }
#pragma unroll
    for (int o = 16; o > 0; o >>= 1)
#pragma unroll
        for (int t = 0; t < 4; t++)
            m[t] = fmaxf(m[t], __shfl_xor_sync(0xffffffffu, m[t], o));

    // pass 2: serial edges, 4 at a time; scores via shfl (j<32)
    float sums[4] = {0.f, 0.f, 0.f, 0.f};
    const int dg32 = dg < 32 ? dg : 32;
    int j = 0;
    for (; j + 3 < dg32; j += 4) {
        int srA = __shfl_sync(0xffffffffu, sr0, j);
        int srB = __shfl_sync(0xffffffffu, sr0, j + 1);
        int srC = __shfl_sync(0xffffffffu, sr0, j + 2);
        int srD = __shfl_sync(0xffffffffu, sr0, j + 3);
        float pA[4], pB[4], pC[4], pD[4];
#pragma unroll
        for (int t = 0; t < 4; t++) {
            float vA = __shfl_sync(0xffffffffu, vv[t], j);
            float vB = __shfl_sync(0xffffffffu, vv[t], j + 1);
            float vC = __shfl_sync(0xffffffffu, vv[t], j + 2);
            float vD = __shfl_sync(0xffffffffu, vv[t], j + 3);
            pA[t] = __expf(vA - m[t]);
            pB[t] = __expf(vB - m[t]);
            pC[t] = __expf(vC - m[t]);
            pD[t] = __expf(vD - m[t]);
            sums[t] += (pA[t] + pB[t]) + (pC[t] + pD[t]);
        }
        const float4* hA = (const float4*)(h + (size_t)srA * F);
        const float4* hB = (const float4*)(h + (size_t)srB * F);
        const float4* hC = (const float4*)(h + (size_t)srC * F);
        const float4* hD = (const float4*)(h + (size_t)srD * F);
#pragma unroll
        for (int c = 0; c < C4; c++) {
            int li = lane + 32 * c;
            int f0 = li * 4;
            float4 hvA = hA[li];
            float4 hvB = hB[li];
            float4 hvC = hC[li];
            float4 hvD = hD[li];
            float pwA = pA[f0 / D], pwB = pB[f0 / D];
            float pwC = pC[f0 / D], pwD = pD[f0 / D];
            acc4[c].x += hvA.x * pwA + hvB.x * pwB + hvC.x * pwC + hvD.x * pwD;
            acc4[c].y += hvA.y * pwA + hvB.y * pwB + hvC.y * pwC + hvD.y * pwD;
            acc4[c].z += hvA.z * pwA + hvB.z * pwB + hvC.z * pwC + hvD.z * pwD;
            acc4[c].w += hvA.w * pwA + hvB.w * pwB + hvC.w * pwC + hvD.w * pwD;
        }
    }
    for (; j + 1 < dg32; j += 2) {
        int srA = __shfl_sync(0xffffffffu, sr0, j);
        int srB = __shfl_sync(0xffffffffu, sr0, j + 1);
        float pA[4], pB[4];
#pragma unroll
        for (int t = 0; t < 4; t++) {
            float vA = __shfl_sync(0xffffffffu, vv[t], j);
            float vB = __shfl_sync(0xffffffffu, vv[t], j + 1);
            pA[t] = __expf(vA - m[t]);
            pB[t] = __expf(vB - m[t]);
            sums[t] += pA[t] + pB[t];
        }
        const float4* hA = (const float4*)(h + (size_t)srA * F);
        const float4* hB = (const float4*)(h + (size_t)srB * F);
#pragma unroll
        for (int c = 0; c < C4; c++) {
            int li = lane + 32 * c;
            int f0 = li * 4;
            float4 hvA = hA[li];
            float4 hvB = hB[li];
            float pwA = pA[f0 / D], pwB = pB[f0 / D];
            acc4[c].x += hvA.x * pwA + hvB.x * pwB;
            acc4[c].y += hvA.y * pwA + hvB.y * pwB;
            acc4[c].z += hvA.z * pwA + hvB.z * pwB;
            acc4[c].w += hvA.w * pwA + hvB.w * pwB;
        }
    }
    if (j < dg32) {
        int sr = __shfl_sync(0xffffffffu, sr0, j);
        float p[4];
#pragma unroll
        for (int t = 0; t < 4; t++) {
            float v = __shfl_sync(0xffffffffu, vv[t], j);
            p[t] = __expf(v - m[t]);
            sums[t] += p[t];
        }
        const float4* hr4 = (const float4*)(h + (size_t)sr * F);
#pragma unroll
        for (int c = 0; c < C4; c++) {
            int li = lane + 32 * c;
            float pw = p[li * 4 / D];
            float4 hv = hr4[li];
            acc4[c].x += hv.x * pw; acc4[c].y += hv.y * pw;
            acc4[c].z += hv.z * pw; acc4[c].w += hv.w * pw;
        }
    }
    for (int jj = 32; jj < dg; jj++) {
        int sr = adj[st + jj];
        float4 sv = sp4[sr];
        float v[4];
        v[0] = sv.x + dd[0]; v[1] = sv.y + dd[1];
        v[2] = sv.z + dd[2]; v[3] = sv.w + dd[3];
        float p[4];
#pragma unroll
        for (int t = 0; t < 4; t++) {
            float x = (v[t] >= 0.f) ? v[t] : 0.2f * v[t];
            p[t] = __expf(x - m[t]);
            sums[t] += p[t];
        }
        const float4* hr4 = (const float4*)(h + (size_t)sr * F);
#pragma unroll
        for (int c = 0; c < C4; c++) {
            int li = lane + 32 * c;
            float pw = p[li * 4 / D];
            float4 hv = hr4[li];
            acc4[c].x += hv.x * pw; acc4[c].y += hv.y * pw;
            acc4[c].z += hv.z * pw; acc4[c].w += hv.w * pw;
        }
    }
    float4* out4 = (float4*)(out + (size_t)w * F);
#pragma unroll
    for (int c = 0; c < C4; c++) {
        int li = lane + 32 * c;
        float inv = 1.f / (sums[li * 4 / D] + 1e-16f);
        float4 v;
        v.x = to_tf32(fmaxf(acc4[c].x * inv, 0.f));
        v.y = to_tf32(fmaxf(acc4[c].y * inv, 0.f));
        v.z = to_tf32(fmaxf(acc4[c].z * inv, 0.f));
        v.w = to_tf32(fmaxf(acc4[c].w * inv, 0.f));
        out4[li] = v;
    }
}

// ---------------------------------------------------------------------------
// Semantic attention
// ---------------------------------------------------------------------------
__global__ void semantic_kernel(const float* __restrict__ wsum,
                                const float* __restrict__ q,
                                float* __restrict__ attn, int F, float invN)
{
    __shared__ float sh0[256], sh1[256];
    int t = threadIdx.x;
    float p0 = 0.f, p1 = 0.f;
    for (int f = t; f < F; f += 256) {
        float qf = q[f];
        p0 += wsum[f] * invN * qf;
        p1 += wsum[F + f] * invN * qf;
    }
    sh0[t] = p0; sh1[t] = p1;
    __syncthreads();
    for (int s = 128; s > 0; s >>= 1) {
        if (t < s) { sh0[t] += sh0[t + s]; sh1[t] += sh1[t + s]; }
        __syncthreads();
    }
    if (t == 0) {
        float m  = fmaxf(sh0[0], sh1[0]);
        float e0 = expf(sh0[0] - m);
        float e1 = expf(sh1[0] - m);
        float inv = 1.f / (e0 + e1);
        attn[0] = e0 * inv;
        attn[1] = e1 * inv;
    }
}

// ---------------------------------------------------------------------------
// Combine (inputs already relu'd): comb = tf32(at0*o0 + at1*o1), float4.
// ---------------------------------------------------------------------------
__global__ void combine_kernel(const float* __restrict__ o0,
                               const float* __restrict__ o1,
                               const float* __restrict__ attn,
                               float* __restrict__ comb, long n4)
{
    long i = (long)blockIdx.x * blockDim.x + threadIdx.x;
    if (i >= n4) return;
    float at0 = attn[0], at1 = attn[1];
    float4 a = ((const float4*)o0)[i];
    float4 b = ((const float4*)o1)[i];
    float4 v;
    v.x = to_tf32(at0 * a.x + at1 * b.x);
    v.y = to_tf32(at0 * a.y + at1 * b.y);
    v.z = to_tf32(at0 * a.z + at1 * b.z);
    v.w = to_tf32(at0 * a.w + at1 * b.w);
    ((float4*)comb)[i] = v;
}

// ---------------------------------------------------------------------------
// Final combine + pool + count, run-length batched (batch is sorted)
// ---------------------------------------------------------------------------
__global__ __launch_bounds__(F2) void combine_pool_count(
    const float* __restrict__ o0, const float* __restrict__ o1,
    const float* __restrict__ attn, const int* __restrict__ batch,
    float* __restrict__ pool, float* __restrict__ cnt, int n)
{
    int f = threadIdx.x;               // 0..127
    int base = blockIdx.x * 128;
    int end  = base + 128 < n ? base + 128 : n;
    if (base >= n) return;
    float at0 = attn[0], at1 = attn[1];
    float acc = 0.f;
    int cur = batch[base];
    int runstart = base;
    for (int i = base; i < end; i++) {
        int g = batch[i];
        if (g != cur) {
            atomicAdd(&pool[cur * F2 + f], acc);
            if (f == 0) atomicAdd(&cnt[cur], (float)(i - runstart));
            acc = 0.f; cur = g; runstart = i;
        }
        size_t off = (size_t)i * F2 + f;
        acc += at0 * o0[off] + at1 * o1[off];
    }
    atomicAdd(&pool[cur * F2 + f], acc);
    if (f == 0) atomicAdd(&cnt[cur], (float)(end - runstart));
}

__global__ void head_kernel(const float* __restrict__ pool,
                            const float* __restrict__ cnt,
                            const float* __restrict__ d1w,
                            const float* __restrict__ d1b,
                            const float* __restrict__ gma,
                            const float* __restrict__ bta,
                            const float* __restrict__ mean,
                            const float* __restrict__ var,
                            const float* __restrict__ d2w,
                            const float* __restrict__ d2b,
                            float* __restrict__ out)
{
    int g = blockIdx.x;
    int j = threadIdx.x;
    float c = fmaxf(cnt[g], 1.f);
    float inv = 1.f / c;
    float acc = d1b[j];
    for (int k = 0; k < F2; k++)
        acc += (pool[g * F2 + k] * inv) * d1w[k * 64 + j];
    acc = (acc - mean[j]) * rsqrtf(var[j] + 1e-5f) * gma[j] + bta[j];
    acc = (acc >= 0.f) ? acc : 0.1f * acc;
    float v = acc * d2w[j];
    __shared__ float red[64];
    red[j] = v;
    __syncthreads();
    for (int s = 32; s > 0; s >>= 1) {
        if (j < s) red[j] += red[j + s];
        __syncthreads();
    }
    if (j == 0) out[g] = red[0] + d2b[0];
}

// ---------------------------------------------------------------------------
// Host orchestration
// ---------------------------------------------------------------------------
static inline int cdiv(long a, int b) { return (int)((a + b - 1) / b); }

extern "C" void kernel_launch(void* const* d_in, const int* in_sizes, int n_in,
                              void* d_out, int out_size)
{
    const float* x       = (const float*)d_in[0];
    const int*   ei0     = (const int*)d_in[1];
    const int*   ei1     = (const int*)d_in[2];
    const int*   batch   = (const int*)d_in[3];
    const float* proj1_w = (const float*)d_in[4];
    const float* proj1_b = (const float*)d_in[5];
    const float* as1_r0  = (const float*)d_in[6];
    const float* ad1_r0  = (const float*)d_in[7];
    const float* as1_r1  = (const float*)d_in[8];
    const float* ad1_r1  = (const float*)d_in[9];
    const float* klin1_w = (const float*)d_in[10];
    const float* klin1_b = (const float*)d_in[11];
    const float* q1      = (const float*)d_in[12];
    const float* proj2_w = (const float*)d_in[13];
    const float* proj2_b = (const float*)d_in[14];
    const float* as2_r0  = (const float*)d_in[15];
    const float* ad2_r0  = (const float*)d_in[16];
    const float* as2_r1  = (const float*)d_in[17];
    const float* ad2_r1  = (const float*)d_in[18];
    const float* klin2_w = (const float*)d_in[19];
    const float* klin2_b = (const float*)d_in[20];
    const float* q2      = (const float*)d_in[21];
    const float* d1_w    = (const float*)d_in[22];
    const float* d1_b    = (const float*)d_in[23];
    const float* bn_g    = (const float*)d_in[24];
    const float* bn_b    = (const float*)d_in[25];
    const float* bn_m    = (const float*)d_in[26];
    const float* bn_v    = (const float*)d_in[27];
    const float* d2_w    = (const float*)d_in[28];
    const float* d2_b    = (const float*)d_in[29];
    float* out = (float*)d_out;

    float *h, *o0, *o1, *comb, *xr, *wa, *wb, *wc, *wd, *s, *d, *wsum, *attn,
          *pool, *cnt;
    int *deg, *rowptr, *cursor, *adj, *partials;
    cudaGetSymbolAddress((void**)&h,       g_h);
    cudaGetSymbolAddress((void**)&o0,      g_out0);
    cudaGetSymbolAddress((void**)&o1,      g_out1);
    cudaGetSymbolAddress((void**)&comb,    g_comb);
    cudaGetSymbolAddress((void**)&xr,      g_x);
    cudaGetSymbolAddress((void**)&wa,      g_wa);
    cudaGetSymbolAddress((void**)&wb,      g_wb);
    cudaGetSymbolAddress((void**)&wc,      g_wc);
    cudaGetSymbolAddress((void**)&wd,      g_wd);
    cudaGetSymbolAddress((void**)&s,       g_s);
    cudaGetSymbolAddress((void**)&d,       g_dd);
    cudaGetSymbolAddress((void**)&wsum,    g_wsum);
    cudaGetSymbolAddress((void**)&attn,    g_attn);
    cudaGetSymbolAddress((void**)&pool,    g_pool);
    cudaGetSymbolAddress((void**)&cnt,     g_cnt);
    cudaGetSymbolAddress((void**)&deg,     g_deg);
    cudaGetSymbolAddress((void**)&rowptr,  g_rowptr);
    cudaGetSymbolAddress((void**)&cursor,  g_cursor);
    cudaGetSymbolAddress((void**)&adj,     g_adj);
    cudaGetSymbolAddress((void**)&partials,g_partials);

    const int n = NNODES, E = NEDGES;
    const int egrid = cdiv(E, 256);
    const int agg_blocks = cdiv(n, 8);

    // ---- launches 1-3: staging; launch #4 = proj1 GEMM (ncu capture) ----
    round_copy<<<cdiv((long)n * 128, 256), 256>>>(x, xr, (long)n * 128);      // 1
    round_copy<<<cdiv(128 * 256, 256), 256>>>(proj1_w, wa, 128 * 256);        // 2
    round_copy<<<cdiv(256 * 256, 256), 256>>>(klin1_w, wb, 256 * 256);        // 3
    {   // 4: proj1 GEMM (profile target / control)
        dim3 grid(F1 / GBN, cdiv(n, GBM), 1);
        mma_gemm_async<<<grid, 256>>>(xr, nullptr, wa, proj1_b, h,
                                      n, 128, F1, 0, nullptr);
    }
    prep_zero<<<cdiv(2 * n, 256), 256>>>(deg, pool, cnt, wsum);
    hist_kernel<<<dim3(egrid, 2), 256>>>(ei0, ei1, deg);
    scan1_kernel<<<dim3(NB, 2), 256>>>(deg, rowptr, partials);
    scan2_kernel<<<2, 256>>>(partials);
    scan3_kernel<<<dim3(NB, 2), 256>>>(rowptr, partials, cursor);
    fillpos_kernel<<<dim3(egrid, 2), 256>>>(ei0, ei1, cursor, adj);
    round_copy<<<cdiv(128 * 128, 256), 256>>>(klin2_w, wc, 128 * 128);
    round_copy<<<cdiv(256 * 128, 256), 256>>>(proj2_w, wd, 256 * 128);

    // ---- Layer 1 (F=256, D=64) ----
    node_scores_kernel<<<cdiv(n * NHEAD, 256), 256>>>(
        h, as1_r0, ad1_r0, as1_r1, ad1_r1, s, d, n, F1, 64);
    agg_kernel<F1, 64><<<dim3(agg_blocks, 2), 256>>>(
        rowptr, deg, adj, h, s, d, o0, o1, n);
    {
        dim3 grid(F1 / GBN, cdiv(n, GBM), 2);
        mma_gemm_async<<<grid, 256>>>(o0, o1, wb, klin1_b, nullptr,
                                      n, F1, F1, 1, wsum);
    }
    semantic_kernel<<<1, 256>>>(wsum, q1, attn, F1, 1.f / n);

    // ---- Layer 2 (F=128, D=32) ----
    combine_kernel<<<cdiv((long)n * F1 / 4, 256), 256>>>(
        o0, o1, attn, comb, (long)n * F1 / 4);
    {
        dim3 grid(F2 / GBN, cdiv(n, GBM), 1);
        mma_gemm_async<<<grid, 256>>>(comb, nullptr, wd, proj2_b, h,
                                      n, F1, F2, 0, nullptr);
    }
    node_scores_kernel<<<cdiv(n * NHEAD, 256), 256>>>(
        h, as2_r0, ad2_r0, as2_r1, ad2_r1, s, d, n, F2, 32);
    agg_kernel<F2, 32><<<dim3(agg_blocks, 2), 256>>>(
        rowptr, deg, adj, h, s, d, o0, o1, n);
    {
        dim3 grid(F2 / GBN, cdiv(n, GBM), 2);
        mma_gemm_async<<<grid, 256>>>(o0, o1, wc, klin2_b, nullptr,
                                      n, F2, F2, 1, wsum + 2 * F1);
    }
    semantic_kernel<<<1, 256>>>(wsum + 2 * F1, q2, attn, F2, 1.f / n);

    // ---- Combine+pool+count (fused, run-length), head ----
    combine_pool_count<<<cdiv(n, 128), F2>>>(o0, o1, attn, batch, pool, cnt, n);
    head_kernel<<<NGRAPH, 64>>>(pool, cnt, d1_w, d1_b, bn_g, bn_b, bn_m, bn_v,
                                d2_w, d2_b, out);
}

// round 13
// speedup vs baseline: 1.0343x; 1.0343x over previous
#include <cuda_runtime.h>
#include <cuda_bf16.h>
#include <cstdint>
#include <math.h>

// Problem constants (match reference)
#define NNODES 50000
#define NEDGES 400000
#define NGRAPH 64
#define NHEAD  4
#define F1 256
#define F2 128
#define NB 196   // ceil(NNODES/256)

// ---------------------------------------------------------------------------
// Device scratch
// ---------------------------------------------------------------------------
__device__ float g_h[NNODES * F1];
__device__ float g_out0[NNODES * F1];
__device__ float g_out1[NNODES * F1];
__device__ float g_comb[NNODES * F1];       // combined layer-1 output (tf32)
__device__ float g_x[NNODES * 128];         // tf32-rounded input features
__device__ float g_wa[128 * 256];           // rounded proj1_w [K][F]
__device__ float g_wb[256 * 256];           // rounded klin1_w
__device__ float g_wc[128 * 128];           // rounded klin2_w
__device__ float g_wd[256 * 128];           // rounded proj2_w
__device__ float g_s[2 * NNODES * NHEAD];
__device__ float g_dd[2 * NNODES * NHEAD];
__device__ float g_wsum[2 * F1 + 2 * F2];   // layer1 @0, layer2 @512
__device__ float g_attn[2];
__device__ float g_pool[NGRAPH * F2];
__device__ float g_cnt[NGRAPH];
// CSR (by dst), 2 relations; adjacency stores SRC node ids directly
__device__ int g_deg[2 * NNODES];
__device__ int g_rowptr[2 * NNODES];
__device__ int g_cursor[2 * NNODES];
__device__ int g_adj[2 * NEDGES];
__device__ int g_partials[2 * NB];

// ---------------------------------------------------------------------------
// Helpers
// ---------------------------------------------------------------------------
__device__ __forceinline__ unsigned to_tf32_bits(float x) {
    unsigned r;
    asm("cvt.rna.tf32.f32 %0, %1;" : "=r"(r) : "f"(x));
    return r;
}
__device__ __forceinline__ float to_tf32(float x) {
    return __uint_as_float(to_tf32_bits(x));
}
__device__ __forceinline__ float tanh_fast(float x) {
    float y;
    asm("tanh.approx.f32 %0, %1;" : "=f"(y) : "f"(x));
    return y;
}

__device__ __forceinline__ void mma_tf32(float c[4],
                                         const unsigned a[4],
                                         const unsigned b[2]) {
    asm volatile(
        "mma.sync.aligned.m16n8k8.row.col.f32.tf32.tf32.f32 "
        "{%0,%1,%2,%3}, {%4,%5,%6,%7}, {%8,%9}, {%0,%1,%2,%3};"
        : "+f"(c[0]), "+f"(c[1]), "+f"(c[2]), "+f"(c[3])
        : "r"(a[0]), "r"(a[1]), "r"(a[2]), "r"(a[3]),
          "r"(b[0]), "r"(b[1]));
}

__device__ __forceinline__ void cp_async16(uint32_t s, const void* g, bool v) {
    int sz = v ? 16 : 0;
    asm volatile("cp.async.ca.shared.global [%0], [%1], 16, %2;"
                 :: "r"(s), "l"(g), "r"(sz));
}
__device__ __forceinline__ void cp_commit() {
    asm volatile("cp.async.commit_group;" ::: "memory");
}
template<int N>
__device__ __forceinline__ void cp_wait() {
    asm volatile("cp.async.wait_group %0;" :: "n"(N) : "memory");
}

__global__ void round_copy(const float* __restrict__ in,
                           float* __restrict__ out, long n) {
    long i = (long)blockIdx.x * blockDim.x + threadIdx.x;
    if (i < n) out[i] = to_tf32(in[i]);
}

// ---------------------------------------------------------------------------
// CSR build kernels
// ---------------------------------------------------------------------------
__global__ void prep_zero(int* __restrict__ deg, float* __restrict__ pool,
                          float* __restrict__ cnt, float* __restrict__ wsum) {
    int i = blockIdx.x * 256 + threadIdx.x;
    if (i < 2 * NNODES) deg[i] = 0;
    if (i < NGRAPH * F2) pool[i] = 0.f;
    if (i < NGRAPH) cnt[i] = 0.f;
    if (i < 2 * F1 + 2 * F2) wsum[i] = 0.f;
}

__global__ void hist_kernel(const int* __restrict__ ei0,
                            const int* __restrict__ ei1,
                            int* __restrict__ deg) {
    int r = blockIdx.y;
    const int* dst = (r == 0 ? ei0 : ei1) + NEDGES;
    int e = blockIdx.x * 256 + threadIdx.x;
    if (e < NEDGES) atomicAdd(&deg[r * NNODES + dst[e]], 1);
}

__global__ void scan1_kernel(const int* __restrict__ deg,
                             int* __restrict__ rowptr,
                             int* __restrict__ partials) {
    int r = blockIdx.y, b = blockIdx.x, t = threadIdx.x;
    int i = b * 256 + t;
    __shared__ int sh[256];
    int v = (i < NNODES) ? deg[r * NNODES + i] : 0;
    sh[t] = v;
    __syncthreads();
    for (int off = 1; off < 256; off <<= 1) {
        int x = (t >= off) ? sh[t - off] : 0;
        __syncthreads();
        sh[t] += x;
        __syncthreads();
    }
    if (i < NNODES) rowptr[r * NNODES + i] = sh[t] - v;  // exclusive
    if (t == 255) partials[r * NB + b] = sh[t];
}

__global__ void scan2_kernel(int* __restrict__ partials) {
    int r = blockIdx.x, t = threadIdx.x;
    __shared__ int sh[256];
    int v = (t < NB) ? partials[r * NB + t] : 0;
    sh[t] = v;
    __syncthreads();
    for (int off = 1; off < 256; off <<= 1) {
        int x = (t >= off) ? sh[t - off] : 0;
        __syncthreads();
        sh[t] += x;
        __syncthreads();
    }
    if (t < NB) partials[r * NB + t] = sh[t] - v;  // exclusive
}

__global__ void scan3_kernel(int* __restrict__ rowptr,
                             const int* __restrict__ partials,
                             int* __restrict__ cursor) {
    int r = blockIdx.y;
    int i = blockIdx.x * 256 + threadIdx.x;
    if (i < NNODES) {
        int v = rowptr[r * NNODES + i] + partials[r * NB + blockIdx.x];
        rowptr[r * NNODES + i] = v;
        cursor[r * NNODES + i] = v;
    }
}

__global__ void fillpos_kernel(const int* __restrict__ ei0,
                               const int* __restrict__ ei1,
                               int* __restrict__ cursor,
                               int* __restrict__ adj) {
    int r = blockIdx.y;
    const int* ei = (r == 0 ? ei0 : ei1);
    int e = blockIdx.x * 256 + threadIdx.x;
    if (e < NEDGES) {
        int pos = atomicAdd(&cursor[r * NNODES + ei[NEDGES + e]], 1);
        adj[r * NEDGES + pos] = ei[e];
    }
}

// ---------------------------------------------------------------------------
// Fast TF32 GEMM (cp.async 4-stage) — measured ~44us on proj1 (CONTROL).
// A pre-rounded [M][K]; W pre-rounded [K][F]. C[M,F] = A @ W (+bias)
// mode 0: C = acc + bias; mode 1: colsum += sum_m tanh(acc + bias)
// grid.z selects A0/A1 (batched klin GEMMs); colsum offset = z*F.
// ---------------------------------------------------------------------------
#define GBM 128
#define GBN 128
#define FBK 8
#define FA_STRIDE 12
#define FB_STRIDE 136
#define FSTAGES 4

__global__ __launch_bounds__(256) void mma_gemm_async(
    const float* __restrict__ A0, const float* __restrict__ A1,
    const float* __restrict__ W,
    const float* __restrict__ bias, float* __restrict__ C,
    int M, int K, int F, int mode, float* __restrict__ colsum)
{
    __shared__ float As[FSTAGES][GBM][FA_STRIDE];   // 24576 B
    __shared__ float Bs[FSTAGES][FBK][FB_STRIDE];   // 17408 B

    const float* __restrict__ A = (blockIdx.z == 0) ? A0 : A1;
    float* cs = (mode == 1) ? colsum + blockIdx.z * F : nullptr;

    const int tid  = threadIdx.x;
    const int lane = tid & 31;
    const int warp = tid >> 5;
    const int wm   = warp & 1;
    const int wn   = warp >> 1;
    const int gid  = lane >> 2;
    const int tig  = lane & 3;

    const int rowBase = blockIdx.y * GBM;
    const int colBase = blockIdx.x * GBN;

    const int a_r = tid >> 1;          // 0..127
    const int a_c = (tid & 1) * 4;     // 0 or 4
    const int b_r = tid >> 5;          // 0..7
    const int b_c = (tid & 31) * 4;    // 0..124
    const bool a_valid = (rowBase + a_r) < M;
    const uint32_t a_sbase = (uint32_t)__cvta_generic_to_shared(&As[0][a_r][a_c]);
    const uint32_t b_sbase = (uint32_t)__cvta_generic_to_shared(&Bs[0][b_r][b_c]);
    const size_t a_goff = (size_t)(rowBase + a_r) * K + a_c;
    const size_t b_goff = (size_t)b_r * F + colBase + b_c;
    const uint32_t a_stage_b = GBM * FA_STRIDE * 4;
    const uint32_t b_stage_b = FBK * FB_STRIDE * 4;

    float acc[4][4][4];
#pragma unroll
    for (int mt = 0; mt < 4; mt++)
#pragma unroll
        for (int nt = 0; nt < 4; nt++)
#pragma unroll
            for (int i = 0; i < 4; i++) acc[mt][nt][i] = 0.f;

    const int KT = K / FBK;

#define ISSUE(stage, kt_) do {                                              \
        cp_async16(a_sbase + (stage) * a_stage_b,                           \
                   A + a_goff + (size_t)(kt_) * FBK, a_valid);              \
        cp_async16(b_sbase + (stage) * b_stage_b,                           \
                   W + b_goff + (size_t)(kt_) * FBK * F, true);             \
        cp_commit();                                                        \
    } while (0)

    ISSUE(0, 0);
    ISSUE(1, 1);
    ISSUE(2, 2);

    for (int kt = 0; kt < KT; kt++) {
        const int rem = KT - kt - 1;
        if (rem >= 2)      cp_wait<2>();
        else if (rem == 1) cp_wait<1>();
        else               cp_wait<0>();
        __syncthreads();

        const int buf = kt & (FSTAGES - 1);
        unsigned afr[4][4], bfr[4][2];
#pragma unroll
        for (int mt = 0; mt < 4; mt++) {
            int r = wm * 64 + mt * 16 + gid;
            afr[mt][0] = __float_as_uint(As[buf][r][tig]);
            afr[mt][1] = __float_as_uint(As[buf][r + 8][tig]);
            afr[mt][2] = __float_as_uint(As[buf][r][tig + 4]);
            afr[mt][3] = __float_as_uint(As[buf][r + 8][tig + 4]);
        }
#pragma unroll
        for (int nt = 0; nt < 4; nt++) {
            int c = wn * 32 + nt * 8 + gid;
            bfr[nt][0] = __float_as_uint(Bs[buf][tig][c]);
            bfr[nt][1] = __float_as_uint(Bs[buf][tig + 4][c]);
        }
#pragma unroll
        for (int mt = 0; mt < 4; mt++)
#pragma unroll
            for (int nt = 0; nt < 4; nt++)
                mma_tf32(acc[mt][nt], afr[mt], bfr[nt]);

        if (kt + FSTAGES - 1 < KT)
            ISSUE((kt + FSTAGES - 1) & (FSTAGES - 1), kt + FSTAGES - 1);
    }
#undef ISSUE

    if (mode == 0) {
#pragma unroll
        for (int mt = 0; mt < 4; mt++) {
            int r0 = rowBase + wm * 64 + mt * 16 + gid;
            int r1 = r0 + 8;
#pragma unroll
            for (int nt = 0; nt < 4; nt++) {
                int gc = colBase + wn * 32 + nt * 8 + tig * 2;
                float b0 = bias[gc], b1 = bias[gc + 1];
                if (r0 < M) {
                    float2 v = make_float2(acc[mt][nt][0] + b0, acc[mt][nt][1] + b1);
                    *reinterpret_cast<float2*>(&C[(size_t)r0 * F + gc]) = v;
                }
                if (r1 < M) {
                    float2 v = make_float2(acc[mt][nt][2] + b0, acc[mt][nt][3] + b1);
                    *reinterpret_cast<float2*>(&C[(size_t)r1 * F + gc]) = v;
                }
            }
        }
    } else {
#pragma unroll
        for (int nt = 0; nt < 4; nt++) {
            int gc = colBase + wn * 32 + nt * 8 + tig * 2;
            float b0 = bias[gc], b1 = bias[gc + 1];
            float csA = 0.f, csB = 0.f;
#pragma unroll
            for (int mt = 0; mt < 4; mt++) {
                int r0 = rowBase + wm * 64 + mt * 16 + gid;
                int r1 = r0 + 8;
                if (r0 < M) {
                    csA += tanh_fast(acc[mt][nt][0] + b0);
                    csB += tanh_fast(acc[mt][nt][1] + b1);
                }
                if (r1 < M) {
                    csA += tanh_fast(acc[mt][nt][2] + b0);
                    csB += tanh_fast(acc[mt][nt][3] + b1);
                }
            }
            // reduce across gid (lanes with same tig share gc): xor 4,8,16
#pragma unroll
            for (int o = 4; o <= 16; o <<= 1) {
                csA += __shfl_xor_sync(0xffffffffu, csA, o);
                csB += __shfl_xor_sync(0xffffffffu, csB, o);
            }
            if (gid == 0) {
                atomicAdd(&cs[gc], csA);
                atomicAdd(&cs[gc + 1], csB);
            }
        }
    }
}

// ---------------------------------------------------------------------------
// Per-(node,head) attention scores, BOTH relations in one pass (h read once)
// ---------------------------------------------------------------------------
__global__ void node_scores_kernel(const float* __restrict__ h,
                                   const float* __restrict__ as0,
                                   const float* __restrict__ ad0,
                                   const float* __restrict__ as1,
                                   const float* __restrict__ ad1,
                                   float* __restrict__ s, float* __restrict__ d,
                                   int n, int F, int D)
{
    int idx = blockIdx.x * blockDim.x + threadIdx.x;
    if (idx >= n * NHEAD) return;
    int node = idx / NHEAD;
    int hh   = idx % NHEAD;
    const float4* hp4 = (const float4*)(h + (size_t)node * F + hh * D);
    const float4* a0 = (const float4*)(as0 + hh * D);
    const float4* b0 = (const float4*)(ad0 + hh * D);
    const float4* a1 = (const float4*)(as1 + hh * D);
    const float4* b1 = (const float4*)(ad1 + hh * D);
    float s0 = 0.f, d0 = 0.f, s1 = 0.f, d1 = 0.f;
    for (int i = 0; i < D / 4; i++) {
        float4 hv = hp4[i];
        float4 av = a0[i], bv = b0[i], cv = a1[i], dv = b1[i];
        s0 += hv.x * av.x + hv.y * av.y + hv.z * av.z + hv.w * av.w;
        d0 += hv.x * bv.x + hv.y * bv.y + hv.z * bv.z + hv.w * bv.w;
        s1 += hv.x * cv.x + hv.y * cv.y + hv.z * cv.z + hv.w * cv.w;
        d1 += hv.x * dv.x + hv.y * dv.y + hv.z * dv.z + hv.w * dv.w;
    }
    s[idx] = s0;               d[idx] = d0;
    s[n * NHEAD + idx] = s1;   d[n * NHEAD + idx] = d1;
}

// ---------------------------------------------------------------------------
// Gather-aggregate: warp per dst node, both relations (grid.y), float4 I/O.
// Pass 1 caches first-wave edge src + scores in regs; pass 2 shuffles them
// and processes TWO edges per iteration (sweet spot for deg~8; R12 showed
// 4-wide regresses).
// ---------------------------------------------------------------------------
template<int F, int D>
__global__ __launch_bounds__(256) void agg_kernel(
    const int* __restrict__ rowptr, const int* __restrict__ deg,
    const int* __restrict__ adjacency,
    const float* __restrict__ h, const float* __restrict__ s,
    const float* __restrict__ dvals,
    float* __restrict__ out0, float* __restrict__ out1, int n)
{
    const int r = blockIdx.y;
    float* __restrict__ out = r == 0 ? out0 : out1;
    const int* rp = rowptr + r * n;
    const int* dgp = deg + r * n;
    const int* __restrict__ adj = adjacency + r * NEDGES;
    const float4* __restrict__ sp4 =
        (const float4*)(s + (size_t)r * n * NHEAD);
    const float4* __restrict__ dp4 =
        (const float4*)(dvals + (size_t)r * n * NHEAD);

    int w = blockIdx.x * (blockDim.x >> 5) + (threadIdx.x >> 5);
    int lane = threadIdx.x & 31;
    if (w >= n) return;
    const int dg = dgp[w];
    const int st = rp[w];
    constexpr int C4 = F / 128;       // float4 per lane
    float4 acc4[C4];
#pragma unroll
    for (int c = 0; c < C4; c++) acc4[c] = make_float4(0.f, 0.f, 0.f, 0.f);
    float4 ddv = dp4[w];
    float dd[4] = {ddv.x, ddv.y, ddv.z, ddv.w};

    // pass 1: per-head max; cache first-wave (j = lane) src + scores
    int sr0 = 0;
    float vv[4] = {0.f, 0.f, 0.f, 0.f};
    float m[4] = {-1e30f, -1e30f, -1e30f, -1e30f};
    for (int j = lane; j < dg; j += 32) {
        int sr = adj[st + j];
        float4 sv = sp4[sr];
        float v[4];
        v[0] = sv.x + dd[0]; v[1] = sv.y + dd[1];
        v[2] = sv.z + dd[2]; v[3] = sv.w + dd[3];
#pragma unroll
        for (int t = 0; t < 4; t++) {
            v[t] = (v[t] >= 0.f) ? v[t] : 0.2f * v[t];
            m[t] = fmaxf(m[t], v[t]);
        }
        if (j == lane) {
            sr0 = sr;
#pragma unroll
            for (int t = 0; t < 4; t++) vv[t] = v[t];
        }
    }
#pragma unroll
    for (int o = 16; o > 0; o >>= 1)
#pragma unroll
        for (int t = 0; t < 4; t++)
            m[t] = fmaxf(m[t], __shfl_xor_sync(0xffffffffu, m[t], o));

    // pass 2: serial edges, 2 at a time; scores via shfl (j<32)
    float sums[4] = {0.f, 0.f, 0.f, 0.f};
    const int dg32 = dg < 32 ? dg : 32;
    int j = 0;
    for (; j + 1 < dg32; j += 2) {
        int srA = __shfl_sync(0xffffffffu, sr0, j);
        int srB = __shfl_sync(0xffffffffu, sr0, j + 1);
        float pA[4], pB[4];
#pragma unroll
        for (int t = 0; t < 4; t++) {
            float vA = __shfl_sync(0xffffffffu, vv[t], j);
            float vB = __shfl_sync(0xffffffffu, vv[t], j + 1);
            pA[t] = __expf(vA - m[t]);
            pB[t] = __expf(vB - m[t]);
            sums[t] += pA[t] + pB[t];
        }
        const float4* hA = (const float4*)(h + (size_t)srA * F);
        const float4* hB = (const float4*)(h + (size_t)srB * F);
#pragma unroll
        for (int c = 0; c < C4; c++) {
            int f0 = (lane + 32 * c) * 4;
            float4 hvA = hA[lane + 32 * c];
            float4 hvB = hB[lane + 32 * c];
            float pwA = pA[f0 / D], pwB = pB[f0 / D];
            acc4[c].x += hvA.x * pwA + hvB.x * pwB;
            acc4[c].y += hvA.y * pwA + hvB.y * pwB;
            acc4[c].z += hvA.z * pwA + hvB.z * pwB;
            acc4[c].w += hvA.w * pwA + hvB.w * pwB;
        }
    }
    if (j < dg32) {
        int sr = __shfl_sync(0xffffffffu, sr0, j);
        float p[4];
#pragma unroll
        for (int t = 0; t < 4; t++) {
            float v = __shfl_sync(0xffffffffu, vv[t], j);
            p[t] = __expf(v - m[t]);
            sums[t] += p[t];
        }
        const float4* hr4 = (const float4*)(h + (size_t)sr * F);
#pragma unroll
        for (int c = 0; c < C4; c++) {
            int f0 = (lane + 32 * c) * 4;
            float pw = p[f0 / D];
            float4 hv = hr4[lane + 32 * c];
            acc4[c].x += hv.x * pw; acc4[c].y += hv.y * pw;
            acc4[c].z += hv.z * pw; acc4[c].w += hv.w * pw;
        }
    }
    for (int jj = 32; jj < dg; jj++) {
        int sr = adj[st + jj];
        float4 sv = sp4[sr];
        float v[4];
        v[0] = sv.x + dd[0]; v[1] = sv.y + dd[1];
        v[2] = sv.z + dd[2]; v[3] = sv.w + dd[3];
        float p[4];
#pragma unroll
        for (int t = 0; t < 4; t++) {
            float x = (v[t] >= 0.f) ? v[t] : 0.2f * v[t];
            p[t] = __expf(x - m[t]);
            sums[t] += p[t];
        }
        const float4* hr4 = (const float4*)(h + (size_t)sr * F);
#pragma unroll
        for (int c = 0; c < C4; c++) {
            int f0 = (lane + 32 * c) * 4;
            float pw = p[f0 / D];
            float4 hv = hr4[lane + 32 * c];
            acc4[c].x += hv.x * pw; acc4[c].y += hv.y * pw;
            acc4[c].z += hv.z * pw; acc4[c].w += hv.w * pw;
        }
    }
    float4* out4 = (float4*)(out + (size_t)w * F);
#pragma unroll
    for (int c = 0; c < C4; c++) {
        int f0 = (lane + 32 * c) * 4;
        float inv = 1.f / (sums[f0 / D] + 1e-16f);
        float4 v;
        v.x = to_tf32(fmaxf(acc4[c].x * inv, 0.f));
        v.y = to_tf32(fmaxf(acc4[c].y * inv, 0.f));
        v.z = to_tf32(fmaxf(acc4[c].z * inv, 0.f));
        v.w = to_tf32(fmaxf(acc4[c].w * inv, 0.f));
        out4[lane + 32 * c] = v;
    }
}

// ---------------------------------------------------------------------------
// Semantic attention
// ---------------------------------------------------------------------------
__global__ void semantic_kernel(const float* __restrict__ wsum,
                                const float* __restrict__ q,
                                float* __restrict__ attn, int F, float invN)
{
    __shared__ float sh0[256], sh1[256];
    int t = threadIdx.x;
    float p0 = 0.f, p1 = 0.f;
    for (int f = t; f < F; f += 256) {
        float qf = q[f];
        p0 += wsum[f] * invN * qf;
        p1 += wsum[F + f] * invN * qf;
    }
    sh0[t] = p0; sh1[t] = p1;
    __syncthreads();
    for (int s = 128; s > 0; s >>= 1) {
        if (t < s) { sh0[t] += sh0[t + s]; sh1[t] += sh1[t + s]; }
        __syncthreads();
    }
    if (t == 0) {
        float m  = fmaxf(sh0[0], sh1[0]);
        float e0 = expf(sh0[0] - m);
        float e1 = expf(sh1[0] - m);
        float inv = 1.f / (e0 + e1);
        attn[0] = e0 * inv;
        attn[1] = e1 * inv;
    }
}

// ---------------------------------------------------------------------------
// Combine (inputs already relu'd): comb = tf32(at0*o0 + at1*o1), float4.
// ---------------------------------------------------------------------------
__global__ void combine_kernel(const float* __restrict__ o0,
                               const float* __restrict__ o1,
                               const float* __restrict__ attn,
                               float* __restrict__ comb, long n4)
{
    long i = (long)blockIdx.x * blockDim.x + threadIdx.x;
    if (i >= n4) return;
    float at0 = attn[0], at1 = attn[1];
    float4 a = ((const float4*)o0)[i];
    float4 b = ((const float4*)o1)[i];
    float4 v;
    v.x = to_tf32(at0 * a.x + at1 * b.x);
    v.y = to_tf32(at0 * a.y + at1 * b.y);
    v.z = to_tf32(at0 * a.z + at1 * b.z);
    v.w = to_tf32(at0 * a.w + at1 * b.w);
    ((float4*)comb)[i] = v;
}

// ---------------------------------------------------------------------------
// Final combine + pool + count, run-length batched (batch is sorted)
// ---------------------------------------------------------------------------
__global__ __launch_bounds__(F2) void combine_pool_count(
    const float* __restrict__ o0, const float* __restrict__ o1,
    const float* __restrict__ attn, const int* __restrict__ batch,
    float* __restrict__ pool, float* __restrict__ cnt, int n)
{
    int f = threadIdx.x;               // 0..127
    int base = blockIdx.x * 128;
    int end  = base + 128 < n ? base + 128 : n;
    if (base >= n) return;
    float at0 = attn[0], at1 = attn[1];
    float acc = 0.f;
    int cur = batch[base];
    int runstart = base;
    for (int i = base; i < end; i++) {
        int g = batch[i];
        if (g != cur) {
            atomicAdd(&pool[cur * F2 + f], acc);
            if (f == 0) atomicAdd(&cnt[cur], (float)(i - runstart));
            acc = 0.f; cur = g; runstart = i;
        }
        size_t off = (size_t)i * F2 + f;
        acc += at0 * o0[off] + at1 * o1[off];
    }
    atomicAdd(&pool[cur * F2 + f], acc);
    if (f == 0) atomicAdd(&cnt[cur], (float)(end - runstart));
}

__global__ void head_kernel(const float* __restrict__ pool,
                            const float* __restrict__ cnt,
                            const float* __restrict__ d1w,
                            const float* __restrict__ d1b,
                            const float* __restrict__ gma,
                            const float* __restrict__ bta,
                            const float* __restrict__ mean,
                            const float* __restrict__ var,
                            const float* __restrict__ d2w,
                            const float* __restrict__ d2b,
                            float* __restrict__ out)
{
    int g = blockIdx.x;
    int j = threadIdx.x;
    float c = fmaxf(cnt[g], 1.f);
    float inv = 1.f / c;
    float acc = d1b[j];
    for (int k = 0; k < F2; k++)
        acc += (pool[g * F2 + k] * inv) * d1w[k * 64 + j];
    acc = (acc - mean[j]) * rsqrtf(var[j] + 1e-5f) * gma[j] + bta[j];
    acc = (acc >= 0.f) ? acc : 0.1f * acc;
    float v = acc * d2w[j];
    __shared__ float red[64];
    red[j] = v;
    __syncthreads();
    for (int s = 32; s > 0; s >>= 1) {
        if (j < s) red[j] += red[j + s];
        __syncthreads();
    }
    if (j == 0) out[g] = red[0] + d2b[0];
}

// ---------------------------------------------------------------------------
// Host orchestration
// ---------------------------------------------------------------------------
static inline int cdiv(long a, int b) { return (int)((a + b - 1) / b); }

extern "C" void kernel_launch(void* const* d_in, const int* in_sizes, int n_in,
                              void* d_out, int out_size)
{
    const float* x       = (const float*)d_in[0];
    const int*   ei0     = (const int*)d_in[1];
    const int*   ei1     = (const int*)d_in[2];
    const int*   batch   = (const int*)d_in[3];
    const float* proj1_w = (const float*)d_in[4];
    const float* proj1_b = (const float*)d_in[5];
    const float* as1_r0  = (const float*)d_in[6];
    const float* ad1_r0  = (const float*)d_in[7];
    const float* as1_r1  = (const float*)d_in[8];
    const float* ad1_r1  = (const float*)d_in[9];
    const float* klin1_w = (const float*)d_in[10];
    const float* klin1_b = (const float*)d_in[11];
    const float* q1      = (const float*)d_in[12];
    const float* proj2_w = (const float*)d_in[13];
    const float* proj2_b = (const float*)d_in[14];
    const float* as2_r0  = (const float*)d_in[15];
    const float* ad2_r0  = (const float*)d_in[16];
    const float* as2_r1  = (const float*)d_in[17];
    const float* ad2_r1  = (const float*)d_in[18];
    const float* klin2_w = (const float*)d_in[19];
    const float* klin2_b = (const float*)d_in[20];
    const float* q2      = (const float*)d_in[21];
    const float* d1_w    = (const float*)d_in[22];
    const float* d1_b    = (const float*)d_in[23];
    const float* bn_g    = (const float*)d_in[24];
    const float* bn_b    = (const float*)d_in[25];
    const float* bn_m    = (const float*)d_in[26];
    const float* bn_v    = (const float*)d_in[27];
    const float* d2_w    = (const float*)d_in[28];
    const float* d2_b    = (const float*)d_in[29];
    float* out = (float*)d_out;

    float *h, *o0, *o1, *comb, *xr, *wa, *wb, *wc, *wd, *s, *d, *wsum, *attn,
          *pool, *cnt;
    int *deg, *rowptr, *cursor, *adj, *partials;
    cudaGetSymbolAddress((void**)&h,       g_h);
    cudaGetSymbolAddress((void**)&o0,      g_out0);
    cudaGetSymbolAddress((void**)&o1,      g_out1);
    cudaGetSymbolAddress((void**)&comb,    g_comb);
    cudaGetSymbolAddress((void**)&xr,      g_x);
    cudaGetSymbolAddress((void**)&wa,      g_wa);
    cudaGetSymbolAddress((void**)&wb,      g_wb);
    cudaGetSymbolAddress((void**)&wc,      g_wc);
    cudaGetSymbolAddress((void**)&wd,      g_wd);
    cudaGetSymbolAddress((void**)&s,       g_s);
    cudaGetSymbolAddress((void**)&d,       g_dd);
    cudaGetSymbolAddress((void**)&wsum,    g_wsum);
    cudaGetSymbolAddress((void**)&attn,    g_attn);
    cudaGetSymbolAddress((void**)&pool,    g_pool);
    cudaGetSymbolAddress((void**)&cnt,     g_cnt);
    cudaGetSymbolAddress((void**)&deg,     g_deg);
    cudaGetSymbolAddress((void**)&rowptr,  g_rowptr);
    cudaGetSymbolAddress((void**)&cursor,  g_cursor);
    cudaGetSymbolAddress((void**)&adj,     g_adj);
    cudaGetSymbolAddress((void**)&partials,g_partials);

    const int n = NNODES, E = NEDGES;
    const int egrid = cdiv(E, 256);
    const int agg_blocks = cdiv(n, 8);

    // ---- launches 1-3: staging; launch #4 = proj1 GEMM (ncu capture) ----
    round_copy<<<cdiv((long)n * 128, 256), 256>>>(x, xr, (long)n * 128);      // 1
    round_copy<<<cdiv(128 * 256, 256), 256>>>(proj1_w, wa, 128 * 256);        // 2
    round_copy<<<cdiv(256 * 256, 256), 256>>>(klin1_w, wb, 256 * 256);        // 3
    {   // 4: proj1 GEMM (profile target / control)
        dim3 grid(F1 / GBN, cdiv(n, GBM), 1);
        mma_gemm_async<<<grid, 256>>>(xr, nullptr, wa, proj1_b, h,
                                      n, 128, F1, 0, nullptr);
    }
    prep_zero<<<cdiv(2 * n, 256), 256>>>(deg, pool, cnt, wsum);
    hist_kernel<<<dim3(egrid, 2), 256>>>(ei0, ei1, deg);
    scan1_kernel<<<dim3(NB, 2), 256>>>(deg, rowptr, partials);
    scan2_kernel<<<2, 256>>>(partials);
    scan3_kernel<<<dim3(NB, 2), 256>>>(rowptr, partials, cursor);
    fillpos_kernel<<<dim3(egrid, 2), 256>>>(ei0, ei1, cursor, adj);
    round_copy<<<cdiv(128 * 128, 256), 256>>>(klin2_w, wc, 128 * 128);
    round_copy<<<cdiv(256 * 128, 256), 256>>>(proj2_w, wd, 256 * 128);

    // ---- Layer 1 (F=256, D=64) ----
    node_scores_kernel<<<cdiv(n * NHEAD, 256), 256>>>(
        h, as1_r0, ad1_r0, as1_r1, ad1_r1, s, d, n, F1, 64);
    agg_kernel<F1, 64><<<dim3(agg_blocks, 2), 256>>>(
        rowptr, deg, adj, h, s, d, o0, o1, n);
    {
        dim3 grid(F1 / GBN, cdiv(n, GBM), 2);
        mma_gemm_async<<<grid, 256>>>(o0, o1, wb, klin1_b, nullptr,
                                      n, F1, F1, 1, wsum);
    }
    semantic_kernel<<<1, 256>>>(wsum, q1, attn, F1, 1.f / n);

    // ---- Layer 2 (F=128, D=32) ----
    combine_kernel<<<cdiv((long)n * F1 / 4, 256), 256>>>(
        o0, o1, attn, comb, (long)n * F1 / 4);
    {
        dim3 grid(F2 / GBN, cdiv(n, GBM), 1);
        mma_gemm_async<<<grid, 256>>>(comb, nullptr, wd, proj2_b, h,
                                      n, F1, F2, 0, nullptr);
    }
    node_scores_kernel<<<cdiv(n * NHEAD, 256), 256>>>(
        h, as2_r0, ad2_r0, as2_r1, ad2_r1, s, d, n, F2, 32);
    agg_kernel<F2, 32><<<dim3(agg_blocks, 2), 256>>>(
        rowptr, deg, adj, h, s, d, o0, o1, n);
    {
        dim3 grid(F2 / GBN, cdiv(n, GBM), 2);
        mma_gemm_async<<<grid, 256>>>(o0, o1, wc, klin2_b, nullptr,
                                      n, F2, F2, 1, wsum + 2 * F1);
    }
    semantic_kernel<<<1, 256>>>(wsum + 2 * F1, q2, attn, F2, 1.f / n);

    // ---- Combine+pool+count (fused, run-length), head ----
    combine_pool_count<<<cdiv(n, 128), F2>>>(o0, o1, attn, batch, pool, cnt, n);
    head_kernel<<<NGRAPH, 64>>>(pool, cnt, d1_w, d1_b, bn_g, bn_b, bn_m, bn_v,
                                d2_w, d2_b, out);
}

// round 14
// speedup vs baseline: 1.0411x; 1.0066x over previous
#include <cuda_runtime.h>
#include <cuda_bf16.h>
#include <cstdint>
#include <math.h>

// Problem constants (match reference)
#define NNODES 50000
#define NEDGES 400000
#define NGRAPH 64
#define NHEAD  4
#define F1 256
#define F2 128
#define NB 196   // ceil(NNODES/256)

// ---------------------------------------------------------------------------
// Device scratch
// ---------------------------------------------------------------------------
__device__ float g_h[NNODES * F1];
__device__ float g_out0[NNODES * F1];
__device__ float g_out1[NNODES * F1];
__device__ float g_comb[NNODES * F1];       // combined layer-1 output (tf32)
__device__ float g_x[NNODES * 128];         // tf32-rounded input features
__device__ float g_wa[128 * 256];           // rounded proj1_w [K][F]
__device__ float g_wb[256 * 256];           // rounded klin1_w
__device__ float g_wc[128 * 128];           // rounded klin2_w
__device__ float g_wd[256 * 128];           // rounded proj2_w
__device__ float g_s[2 * NNODES * NHEAD];
__device__ float g_dd[2 * NNODES * NHEAD];
__device__ float g_wsum[2 * F1 + 2 * F2];   // layer1 @0, layer2 @512
__device__ float g_attn[2];
__device__ float g_pool[NGRAPH * F2];
__device__ float g_cnt[NGRAPH];
// CSR (by dst), 2 relations; adjacency stores SRC node ids directly
__device__ int g_deg[2 * NNODES];
__device__ int g_rowptr[2 * NNODES];
__device__ int g_cursor[2 * NNODES];
__device__ int g_adj[2 * NEDGES];
__device__ int g_partials[2 * NB];

// ---------------------------------------------------------------------------
// Helpers
// ---------------------------------------------------------------------------
__device__ __forceinline__ unsigned to_tf32_bits(float x) {
    unsigned r;
    asm("cvt.rna.tf32.f32 %0, %1;" : "=r"(r) : "f"(x));
    return r;
}
__device__ __forceinline__ float to_tf32(float x) {
    return __uint_as_float(to_tf32_bits(x));
}
__device__ __forceinline__ float tanh_fast(float x) {
    float y;
    asm("tanh.approx.f32 %0, %1;" : "=f"(y) : "f"(x));
    return y;
}

__device__ __forceinline__ void mma_tf32(float c[4],
                                         const unsigned a[4],
                                         const unsigned b[2]) {
    asm volatile(
        "mma.sync.aligned.m16n8k8.row.col.f32.tf32.tf32.f32 "
        "{%0,%1,%2,%3}, {%4,%5,%6,%7}, {%8,%9}, {%0,%1,%2,%3};"
        : "+f"(c[0]), "+f"(c[1]), "+f"(c[2]), "+f"(c[3])
        : "r"(a[0]), "r"(a[1]), "r"(a[2]), "r"(a[3]),
          "r"(b[0]), "r"(b[1]));
}

__device__ __forceinline__ void cp_async16(uint32_t s, const void* g, bool v) {
    int sz = v ? 16 : 0;
    asm volatile("cp.async.ca.shared.global [%0], [%1], 16, %2;"
                 :: "r"(s), "l"(g), "r"(sz));
}
__device__ __forceinline__ void cp_commit() {
    asm volatile("cp.async.commit_group;" ::: "memory");
}
template<int N>
__device__ __forceinline__ void cp_wait() {
    asm volatile("cp.async.wait_group %0;" :: "n"(N) : "memory");
}

__global__ void round_copy(const float* __restrict__ in,
                           float* __restrict__ out, long n) {
    long i = (long)blockIdx.x * blockDim.x + threadIdx.x;
    if (i < n) out[i] = to_tf32(in[i]);
}

// ---------------------------------------------------------------------------
// CSR build kernels
// ---------------------------------------------------------------------------
__global__ void prep_zero(int* __restrict__ deg, float* __restrict__ pool,
                          float* __restrict__ cnt, float* __restrict__ wsum) {
    int i = blockIdx.x * 256 + threadIdx.x;
    if (i < 2 * NNODES) deg[i] = 0;
    if (i < NGRAPH * F2) pool[i] = 0.f;
    if (i < NGRAPH) cnt[i] = 0.f;
    if (i < 2 * F1 + 2 * F2) wsum[i] = 0.f;
}

__global__ void hist_kernel(const int* __restrict__ ei0,
                            const int* __restrict__ ei1,
                            int* __restrict__ deg) {
    int r = blockIdx.y;
    const int* dst = (r == 0 ? ei0 : ei1) + NEDGES;
    int e = blockIdx.x * 256 + threadIdx.x;
    if (e < NEDGES) atomicAdd(&deg[r * NNODES + dst[e]], 1);
}

__global__ void scan1_kernel(const int* __restrict__ deg,
                             int* __restrict__ rowptr,
                             int* __restrict__ partials) {
    int r = blockIdx.y, b = blockIdx.x, t = threadIdx.x;
    int i = b * 256 + t;
    __shared__ int sh[256];
    int v = (i < NNODES) ? deg[r * NNODES + i] : 0;
    sh[t] = v;
    __syncthreads();
    for (int off = 1; off < 256; off <<= 1) {
        int x = (t >= off) ? sh[t - off] : 0;
        __syncthreads();
        sh[t] += x;
        __syncthreads();
    }
    if (i < NNODES) rowptr[r * NNODES + i] = sh[t] - v;  // exclusive
    if (t == 255) partials[r * NB + b] = sh[t];
}

__global__ void scan2_kernel(int* __restrict__ partials) {
    int r = blockIdx.x, t = threadIdx.x;
    __shared__ int sh[256];
    int v = (t < NB) ? partials[r * NB + t] : 0;
    sh[t] = v;
    __syncthreads();
    for (int off = 1; off < 256; off <<= 1) {
        int x = (t >= off) ? sh[t - off] : 0;
        __syncthreads();
        sh[t] += x;
        __syncthreads();
    }
    if (t < NB) partials[r * NB + t] = sh[t] - v;  // exclusive
}

__global__ void scan3_kernel(int* __restrict__ rowptr,
                             const int* __restrict__ partials,
                             int* __restrict__ cursor) {
    int r = blockIdx.y;
    int i = blockIdx.x * 256 + threadIdx.x;
    if (i < NNODES) {
        int v = rowptr[r * NNODES + i] + partials[r * NB + blockIdx.x];
        rowptr[r * NNODES + i] = v;
        cursor[r * NNODES + i] = v;
    }
}

__global__ void fillpos_kernel(const int* __restrict__ ei0,
                               const int* __restrict__ ei1,
                               int* __restrict__ cursor,
                               int* __restrict__ adj) {
    int r = blockIdx.y;
    const int* ei = (r == 0 ? ei0 : ei1);
    int e = blockIdx.x * 256 + threadIdx.x;
    if (e < NEDGES) {
        int pos = atomicAdd(&cursor[r * NNODES + ei[NEDGES + e]], 1);
        adj[r * NEDGES + pos] = ei[e];
    }
}

// ---------------------------------------------------------------------------
// Fast TF32 GEMM (cp.async 4-stage) with k-pair slot remap:
// quad-thread tig supplies k = {2*tig, 2*tig+1} (valid: the quad contraction
// only requires A/B slots to pair identical k — verified in R8 correctness).
// A tile stride 8 words (unpadded): A fragment LDS.64 at 8*(row)+2*tig is
// bank-conflict-free (gid phase offsets {0,8,16,24}).
// B tile stride 132 (==4 mod 32): rows 2*tig at offsets {0,8,16,24},
// rows 2*tig+1 at {4,12,20,28} — both scalar B loads conflict-free.
// A pre-rounded [M][K]; W pre-rounded [K][F]. C[M,F] = A @ W (+bias)
// mode 0: C = acc + bias; mode 1: colsum += sum_m tanh(acc + bias)
// grid.z selects A0/A1 (batched klin GEMMs); colsum offset = z*F.
// ---------------------------------------------------------------------------
#define GBM 128
#define GBN 128
#define FBK 8
#define FA_STRIDE 8
#define FB_STRIDE 132
#define FSTAGES 4

__global__ __launch_bounds__(256) void mma_gemm_async(
    const float* __restrict__ A0, const float* __restrict__ A1,
    const float* __restrict__ W,
    const float* __restrict__ bias, float* __restrict__ C,
    int M, int K, int F, int mode, float* __restrict__ colsum)
{
    __shared__ float As[FSTAGES][GBM][FA_STRIDE];   // 16384 B
    __shared__ float Bs[FSTAGES][FBK][FB_STRIDE];   // 16896 B

    const float* __restrict__ A = (blockIdx.z == 0) ? A0 : A1;
    float* cs = (mode == 1) ? colsum + blockIdx.z * F : nullptr;

    const int tid  = threadIdx.x;
    const int lane = tid & 31;
    const int warp = tid >> 5;
    const int wm   = warp & 1;
    const int wn   = warp >> 1;
    const int gid  = lane >> 2;
    const int tig  = lane & 3;
    const int k2   = tig * 2;

    const int rowBase = blockIdx.y * GBM;
    const int colBase = blockIdx.x * GBN;

    const int a_r = tid >> 1;          // 0..127
    const int a_c = (tid & 1) * 4;     // 0 or 4
    const int b_r = tid >> 5;          // 0..7
    const int b_c = (tid & 31) * 4;    // 0..124
    const bool a_valid = (rowBase + a_r) < M;
    const uint32_t a_sbase = (uint32_t)__cvta_generic_to_shared(&As[0][a_r][a_c]);
    const uint32_t b_sbase = (uint32_t)__cvta_generic_to_shared(&Bs[0][b_r][b_c]);
    const size_t a_goff = (size_t)(rowBase + a_r) * K + a_c;
    const size_t b_goff = (size_t)b_r * F + colBase + b_c;
    const uint32_t a_stage_b = GBM * FA_STRIDE * 4;
    const uint32_t b_stage_b = FBK * FB_STRIDE * 4;

    float acc[4][4][4];
#pragma unroll
    for (int mt = 0; mt < 4; mt++)
#pragma unroll
        for (int nt = 0; nt < 4; nt++)
#pragma unroll
            for (int i = 0; i < 4; i++) acc[mt][nt][i] = 0.f;

    const int KT = K / FBK;

#define ISSUE(stage, kt_) do {                                              \
        cp_async16(a_sbase + (stage) * a_stage_b,                           \
                   A + a_goff + (size_t)(kt_) * FBK, a_valid);              \
        cp_async16(b_sbase + (stage) * b_stage_b,                           \
                   W + b_goff + (size_t)(kt_) * FBK * F, true);             \
        cp_commit();                                                        \
    } while (0)

    ISSUE(0, 0);
    ISSUE(1, 1);
    ISSUE(2, 2);

    for (int kt = 0; kt < KT; kt++) {
        const int rem = KT - kt - 1;
        if (rem >= 2)      cp_wait<2>();
        else if (rem == 1) cp_wait<1>();
        else               cp_wait<0>();
        __syncthreads();

        const int buf = kt & (FSTAGES - 1);
        unsigned afr[4][4], bfr[4][2];
#pragma unroll
        for (int mt = 0; mt < 4; mt++) {
            int r = wm * 64 + mt * 16 + gid;
            float2 lo = *reinterpret_cast<const float2*>(&As[buf][r][k2]);
            float2 hi = *reinterpret_cast<const float2*>(&As[buf][r + 8][k2]);
            afr[mt][0] = __float_as_uint(lo.x);
            afr[mt][1] = __float_as_uint(hi.x);
            afr[mt][2] = __float_as_uint(lo.y);
            afr[mt][3] = __float_as_uint(hi.y);
        }
#pragma unroll
        for (int nt = 0; nt < 4; nt++) {
            int c = wn * 32 + nt * 8 + gid;
            bfr[nt][0] = __float_as_uint(Bs[buf][k2][c]);
            bfr[nt][1] = __float_as_uint(Bs[buf][k2 + 1][c]);
        }
#pragma unroll
        for (int mt = 0; mt < 4; mt++)
#pragma unroll
            for (int nt = 0; nt < 4; nt++)
                mma_tf32(acc[mt][nt], afr[mt], bfr[nt]);

        if (kt + FSTAGES - 1 < KT)
            ISSUE((kt + FSTAGES - 1) & (FSTAGES - 1), kt + FSTAGES - 1);
    }
#undef ISSUE

    if (mode == 0) {
#pragma unroll
        for (int mt = 0; mt < 4; mt++) {
            int r0 = rowBase + wm * 64 + mt * 16 + gid;
            int r1 = r0 + 8;
#pragma unroll
            for (int nt = 0; nt < 4; nt++) {
                int gc = colBase + wn * 32 + nt * 8 + tig * 2;
                float b0 = bias[gc], b1 = bias[gc + 1];
                if (r0 < M) {
                    float2 v = make_float2(acc[mt][nt][0] + b0, acc[mt][nt][1] + b1);
                    *reinterpret_cast<float2*>(&C[(size_t)r0 * F + gc]) = v;
                }
                if (r1 < M) {
                    float2 v = make_float2(acc[mt][nt][2] + b0, acc[mt][nt][3] + b1);
                    *reinterpret_cast<float2*>(&C[(size_t)r1 * F + gc]) = v;
                }
            }
        }
    } else {
#pragma unroll
        for (int nt = 0; nt < 4; nt++) {
            int gc = colBase + wn * 32 + nt * 8 + tig * 2;
            float b0 = bias[gc], b1 = bias[gc + 1];
            float csA = 0.f, csB = 0.f;
#pragma unroll
            for (int mt = 0; mt < 4; mt++) {
                int r0 = rowBase + wm * 64 + mt * 16 + gid;
                int r1 = r0 + 8;
                if (r0 < M) {
                    csA += tanh_fast(acc[mt][nt][0] + b0);
                    csB += tanh_fast(acc[mt][nt][1] + b1);
                }
                if (r1 < M) {
                    csA += tanh_fast(acc[mt][nt][2] + b0);
                    csB += tanh_fast(acc[mt][nt][3] + b1);
                }
            }
            // reduce across gid (lanes with same tig share gc): xor 4,8,16
#pragma unroll
            for (int o = 4; o <= 16; o <<= 1) {
                csA += __shfl_xor_sync(0xffffffffu, csA, o);
                csB += __shfl_xor_sync(0xffffffffu, csB, o);
            }
            if (gid == 0) {
                atomicAdd(&cs[gc], csA);
                atomicAdd(&cs[gc + 1], csB);
            }
        }
    }
}

// ---------------------------------------------------------------------------
// Per-(node,head) attention scores, BOTH relations in one pass (h read once)
// ---------------------------------------------------------------------------
__global__ void node_scores_kernel(const float* __restrict__ h,
                                   const float* __restrict__ as0,
                                   const float* __restrict__ ad0,
                                   const float* __restrict__ as1,
                                   const float* __restrict__ ad1,
                                   float* __restrict__ s, float* __restrict__ d,
                                   int n, int F, int D)
{
    int idx = blockIdx.x * blockDim.x + threadIdx.x;
    if (idx >= n * NHEAD) return;
    int node = idx / NHEAD;
    int hh   = idx % NHEAD;
    const float4* hp4 = (const float4*)(h + (size_t)node * F + hh * D);
    const float4* a0 = (const float4*)(as0 + hh * D);
    const float4* b0 = (const float4*)(ad0 + hh * D);
    const float4* a1 = (const float4*)(as1 + hh * D);
    const float4* b1 = (const float4*)(ad1 + hh * D);
    float s0 = 0.f, d0 = 0.f, s1 = 0.f, d1 = 0.f;
    for (int i = 0; i < D / 4; i++) {
        float4 hv = hp4[i];
        float4 av = a0[i], bv = b0[i], cv = a1[i], dv = b1[i];
        s0 += hv.x * av.x + hv.y * av.y + hv.z * av.z + hv.w * av.w;
        d0 += hv.x * bv.x + hv.y * bv.y + hv.z * bv.z + hv.w * bv.w;
        s1 += hv.x * cv.x + hv.y * cv.y + hv.z * cv.z + hv.w * cv.w;
        d1 += hv.x * dv.x + hv.y * dv.y + hv.z * dv.z + hv.w * dv.w;
    }
    s[idx] = s0;               d[idx] = d0;
    s[n * NHEAD + idx] = s1;   d[n * NHEAD + idx] = d1;
}

// ---------------------------------------------------------------------------
// Gather-aggregate: warp per dst node, both relations (grid.y), float4 I/O.
// Pass 1 caches first-wave edge src + scores in regs; pass 2 shuffles them
// and processes TWO edges per iteration (sweet spot for deg~8).
// ---------------------------------------------------------------------------
template<int F, int D>
__global__ __launch_bounds__(256) void agg_kernel(
    const int* __restrict__ rowptr, const int* __restrict__ deg,
    const int* __restrict__ adjacency,
    const float* __restrict__ h, const float* __restrict__ s,
    const float* __restrict__ dvals,
    float* __restrict__ out0, float* __restrict__ out1, int n)
{
    const int r = blockIdx.y;
    float* __restrict__ out = r == 0 ? out0 : out1;
    const int* rp = rowptr + r * n;
    const int* dgp = deg + r * n;
    const int* __restrict__ adj = adjacency + r * NEDGES;
    const float4* __restrict__ sp4 =
        (const float4*)(s + (size_t)r * n * NHEAD);
    const float4* __restrict__ dp4 =
        (const float4*)(dvals + (size_t)r * n * NHEAD);

    int w = blockIdx.x * (blockDim.x >> 5) + (threadIdx.x >> 5);
    int lane = threadIdx.x & 31;
    if (w >= n) return;
    const int dg = dgp[w];
    const int st = rp[w];
    constexpr int C4 = F / 128;       // float4 per lane
    float4 acc4[C4];
#pragma unroll
    for (int c = 0; c < C4; c++) acc4[c] = make_float4(0.f, 0.f, 0.f, 0.f);
    float4 ddv = dp4[w];
    float dd[4] = {ddv.x, ddv.y, ddv.z, ddv.w};

    // pass 1: per-head max; cache first-wave (j = lane) src + scores
    int sr0 = 0;
    float vv[4] = {0.f, 0.f, 0.f, 0.f};
    float m[4] = {-1e30f, -1e30f, -1e30f, -1e30f};
    for (int j = lane; j < dg; j += 32) {
        int sr = adj[st + j];
        float4 sv = sp4[sr];
        float v[4];
        v[0] = sv.x + dd[0]; v[1] = sv.y + dd[1];
        v[2] = sv.z + dd[2]; v[3] = sv.w + dd[3];
#pragma unroll
        for (int t = 0; t < 4; t++) {
            v[t] = (v[t] >= 0.f) ? v[t] : 0.2f * v[t];
            m[t] = fmaxf(m[t], v[t]);
        }
        if (j == lane) {
            sr0 = sr;
#pragma unroll
            for (int t = 0; t < 4; t++) vv[t] = v[t];
        }
    }
#pragma unroll
    for (int o = 16; o > 0; o >>= 1)
#pragma unroll
        for (int t = 0; t < 4; t++)
            m[t] = fmaxf(m[t], __shfl_xor_sync(0xffffffffu, m[t], o));

    // pass 2: serial edges, 2 at a time; scores via shfl (j<32)
    float sums[4] = {0.f, 0.f, 0.f, 0.f};
    const int dg32 = dg < 32 ? dg : 32;
    int j = 0;
    for (; j + 1 < dg32; j += 2) {
        int srA = __shfl_sync(0xffffffffu, sr0, j);
        int srB = __shfl_sync(0xffffffffu, sr0, j + 1);
        float pA[4], pB[4];
#pragma unroll
        for (int t = 0; t < 4; t++) {
            float vA = __shfl_sync(0xffffffffu, vv[t], j);
            float vB = __shfl_sync(0xffffffffu, vv[t], j + 1);
            pA[t] = __expf(vA - m[t]);
            pB[t] = __expf(vB - m[t]);
            sums[t] += pA[t] + pB[t];
        }
        const float4* hA = (const float4*)(h + (size_t)srA * F);
        const float4* hB = (const float4*)(h + (size_t)srB * F);
#pragma unroll
        for (int c = 0; c < C4; c++) {
            int f0 = (lane + 32 * c) * 4;
            float4 hvA = hA[lane + 32 * c];
            float4 hvB = hB[lane + 32 * c];
            float pwA = pA[f0 / D], pwB = pB[f0 / D];
            acc4[c].x += hvA.x * pwA + hvB.x * pwB;
            acc4[c].y += hvA.y * pwA + hvB.y * pwB;
            acc4[c].z += hvA.z * pwA + hvB.z * pwB;
            acc4[c].w += hvA.w * pwA + hvB.w * pwB;
        }
    }
    if (j < dg32) {
        int sr = __shfl_sync(0xffffffffu, sr0, j);
        float p[4];
#pragma unroll
        for (int t = 0; t < 4; t++) {
            float v = __shfl_sync(0xffffffffu, vv[t], j);
            p[t] = __expf(v - m[t]);
            sums[t] += p[t];
        }
        const float4* hr4 = (const float4*)(h + (size_t)sr * F);
#pragma unroll
        for (int c = 0; c < C4; c++) {
            int f0 = (lane + 32 * c) * 4;
            float pw = p[f0 / D];
            float4 hv = hr4[lane + 32 * c];
            acc4[c].x += hv.x * pw; acc4[c].y += hv.y * pw;
            acc4[c].z += hv.z * pw; acc4[c].w += hv.w * pw;
        }
    }
    for (int jj = 32; jj < dg; jj++) {
        int sr = adj[st + jj];
        float4 sv = sp4[sr];
        float v[4];
        v[0] = sv.x + dd[0]; v[1] = sv.y + dd[1];
        v[2] = sv.z + dd[2]; v[3] = sv.w + dd[3];
        float p[4];
#pragma unroll
        for (int t = 0; t < 4; t++) {
            float x = (v[t] >= 0.f) ? v[t] : 0.2f * v[t];
            p[t] = __expf(x - m[t]);
            sums[t] += p[t];
        }
        const float4* hr4 = (const float4*)(h + (size_t)sr * F);
#pragma unroll
        for (int c = 0; c < C4; c++) {
            int f0 = (lane + 32 * c) * 4;
            float pw = p[f0 / D];
            float4 hv = hr4[lane + 32 * c];
            acc4[c].x += hv.x * pw; acc4[c].y += hv.y * pw;
            acc4[c].z += hv.z * pw; acc4[c].w += hv.w * pw;
        }
    }
    float4* out4 = (float4*)(out + (size_t)w * F);
#pragma unroll
    for (int c = 0; c < C4; c++) {
        int f0 = (lane + 32 * c) * 4;
        float inv = 1.f / (sums[f0 / D] + 1e-16f);
        float4 v;
        v.x = to_tf32(fmaxf(acc4[c].x * inv, 0.f));
        v.y = to_tf32(fmaxf(acc4[c].y * inv, 0.f));
        v.z = to_tf32(fmaxf(acc4[c].z * inv, 0.f));
        v.w = to_tf32(fmaxf(acc4[c].w * inv, 0.f));
        out4[lane + 32 * c] = v;
    }
}

// ---------------------------------------------------------------------------
// Semantic attention
// ---------------------------------------------------------------------------
__global__ void semantic_kernel(const float* __restrict__ wsum,
                                const float* __restrict__ q,
                                float* __restrict__ attn, int F, float invN)
{
    __shared__ float sh0[256], sh1[256];
    int t = threadIdx.x;
    float p0 = 0.f, p1 = 0.f;
    for (int f = t; f < F; f += 256) {
        float qf = q[f];
        p0 += wsum[f] * invN * qf;
        p1 += wsum[F + f] * invN * qf;
    }
    sh0[t] = p0; sh1[t] = p1;
    __syncthreads();
    for (int s = 128; s > 0; s >>= 1) {
        if (t < s) { sh0[t] += sh0[t + s]; sh1[t] += sh1[t + s]; }
        __syncthreads();
    }
    if (t == 0) {
        float m  = fmaxf(sh0[0], sh1[0]);
        float e0 = expf(sh0[0] - m);
        float e1 = expf(sh1[0] - m);
        float inv = 1.f / (e0 + e1);
        attn[0] = e0 * inv;
        attn[1] = e1 * inv;
    }
}

// ---------------------------------------------------------------------------
// Combine (inputs already relu'd): comb = tf32(at0*o0 + at1*o1), float4.
// ---------------------------------------------------------------------------
__global__ void combine_kernel(const float* __restrict__ o0,
                               const float* __restrict__ o1,
                               const float* __restrict__ attn,
                               float* __restrict__ comb, long n4)
{
    long i = (long)blockIdx.x * blockDim.x + threadIdx.x;
    if (i >= n4) return;
    float at0 = attn[0], at1 = attn[1];
    float4 a = ((const float4*)o0)[i];
    float4 b = ((const float4*)o1)[i];
    float4 v;
    v.x = to_tf32(at0 * a.x + at1 * b.x);
    v.y = to_tf32(at0 * a.y + at1 * b.y);
    v.z = to_tf32(at0 * a.z + at1 * b.z);
    v.w = to_tf32(at0 * a.w + at1 * b.w);
    ((float4*)comb)[i] = v;
}

// ---------------------------------------------------------------------------
// Final combine + pool + count, run-length batched (batch is sorted)
// ---------------------------------------------------------------------------
__global__ __launch_bounds__(F2) void combine_pool_count(
    const float* __restrict__ o0, const float* __restrict__ o1,
    const float* __restrict__ attn, const int* __restrict__ batch,
    float* __restrict__ pool, float* __restrict__ cnt, int n)
{
    int f = threadIdx.x;               // 0..127
    int base = blockIdx.x * 128;
    int end  = base + 128 < n ? base + 128 : n;
    if (base >= n) return;
    float at0 = attn[0], at1 = attn[1];
    float acc = 0.f;
    int cur = batch[base];
    int runstart = base;
    for (int i = base; i < end; i++) {
        int g = batch[i];
        if (g != cur) {
            atomicAdd(&pool[cur * F2 + f], acc);
            if (f == 0) atomicAdd(&cnt[cur], (float)(i - runstart));
            acc = 0.f; cur = g; runstart = i;
        }
        size_t off = (size_t)i * F2 + f;
        acc += at0 * o0[off] + at1 * o1[off];
    }
    atomicAdd(&pool[cur * F2 + f], acc);
    if (f == 0) atomicAdd(&cnt[cur], (float)(end - runstart));
}

__global__ void head_kernel(const float* __restrict__ pool,
                            const float* __restrict__ cnt,
                            const float* __restrict__ d1w,
                            const float* __restrict__ d1b,
                            const float* __restrict__ gma,
                            const float* __restrict__ bta,
                            const float* __restrict__ mean,
                            const float* __restrict__ var,
                            const float* __restrict__ d2w,
                            const float* __restrict__ d2b,
                            float* __restrict__ out)
{
    int g = blockIdx.x;
    int j = threadIdx.x;
    float c = fmaxf(cnt[g], 1.f);
    float inv = 1.f / c;
    float acc = d1b[j];
    for (int k = 0; k < F2; k++)
        acc += (pool[g * F2 + k] * inv) * d1w[k * 64 + j];
    acc = (acc - mean[j]) * rsqrtf(var[j] + 1e-5f) * gma[j] + bta[j];
    acc = (acc >= 0.f) ? acc : 0.1f * acc;
    float v = acc * d2w[j];
    __shared__ float red[64];
    red[j] = v;
    __syncthreads();
    for (int s = 32; s > 0; s >>= 1) {
        if (j < s) red[j] += red[j + s];
        __syncthreads();
    }
    if (j == 0) out[g] = red[0] + d2b[0];
}

// ---------------------------------------------------------------------------
// Host orchestration
// ---------------------------------------------------------------------------
static inline int cdiv(long a, int b) { return (int)((a + b - 1) / b); }

extern "C" void kernel_launch(void* const* d_in, const int* in_sizes, int n_in,
                              void* d_out, int out_size)
{
    const float* x       = (const float*)d_in[0];
    const int*   ei0     = (const int*)d_in[1];
    const int*   ei1     = (const int*)d_in[2];
    const int*   batch   = (const int*)d_in[3];
    const float* proj1_w = (const float*)d_in[4];
    const float* proj1_b = (const float*)d_in[5];
    const float* as1_r0  = (const float*)d_in[6];
    const float* ad1_r0  = (const float*)d_in[7];
    const float* as1_r1  = (const float*)d_in[8];
    const float* ad1_r1  = (const float*)d_in[9];
    const float* klin1_w = (const float*)d_in[10];
    const float* klin1_b = (const float*)d_in[11];
    const float* q1      = (const float*)d_in[12];
    const float* proj2_w = (const float*)d_in[13];
    const float* proj2_b = (const float*)d_in[14];
    const float* as2_r0  = (const float*)d_in[15];
    const float* ad2_r0  = (const float*)d_in[16];
    const float* as2_r1  = (const float*)d_in[17];
    const float* ad2_r1  = (const float*)d_in[18];
    const float* klin2_w = (const float*)d_in[19];
    const float* klin2_b = (const float*)d_in[20];
    const float* q2      = (const float*)d_in[21];
    const float* d1_w    = (const float*)d_in[22];
    const float* d1_b    = (const float*)d_in[23];
    const float* bn_g    = (const float*)d_in[24];
    const float* bn_b    = (const float*)d_in[25];
    const float* bn_m    = (const float*)d_in[26];
    const float* bn_v    = (const float*)d_in[27];
    const float* d2_w    = (const float*)d_in[28];
    const float* d2_b    = (const float*)d_in[29];
    float* out = (float*)d_out;

    float *h, *o0, *o1, *comb, *xr, *wa, *wb, *wc, *wd, *s, *d, *wsum, *attn,
          *pool, *cnt;
    int *deg, *rowptr, *cursor, *adj, *partials;
    cudaGetSymbolAddress((void**)&h,       g_h);
    cudaGetSymbolAddress((void**)&o0,      g_out0);
    cudaGetSymbolAddress((void**)&o1,      g_out1);
    cudaGetSymbolAddress((void**)&comb,    g_comb);
    cudaGetSymbolAddress((void**)&xr,      g_x);
    cudaGetSymbolAddress((void**)&wa,      g_wa);
    cudaGetSymbolAddress((void**)&wb,      g_wb);
    cudaGetSymbolAddress((void**)&wc,      g_wc);
    cudaGetSymbolAddress((void**)&wd,      g_wd);
    cudaGetSymbolAddress((void**)&s,       g_s);
    cudaGetSymbolAddress((void**)&d,       g_dd);
    cudaGetSymbolAddress((void**)&wsum,    g_wsum);
    cudaGetSymbolAddress((void**)&attn,    g_attn);
    cudaGetSymbolAddress((void**)&pool,    g_pool);
    cudaGetSymbolAddress((void**)&cnt,     g_cnt);
    cudaGetSymbolAddress((void**)&deg,     g_deg);
    cudaGetSymbolAddress((void**)&rowptr,  g_rowptr);
    cudaGetSymbolAddress((void**)&cursor,  g_cursor);
    cudaGetSymbolAddress((void**)&adj,     g_adj);
    cudaGetSymbolAddress((void**)&partials,g_partials);

    const int n = NNODES, E = NEDGES;
    const int egrid = cdiv(E, 256);
    const int agg_blocks = cdiv(n, 8);

    // ---- launches 1-3: staging; launch #4 = proj1 GEMM (ncu capture) ----
    round_copy<<<cdiv((long)n * 128, 256), 256>>>(x, xr, (long)n * 128);      // 1
    round_copy<<<cdiv(128 * 256, 256), 256>>>(proj1_w, wa, 128 * 256);        // 2
    round_copy<<<cdiv(256 * 256, 256), 256>>>(klin1_w, wb, 256 * 256);        // 3
    {   // 4: proj1 GEMM (profile target)
        dim3 grid(F1 / GBN, cdiv(n, GBM), 1);
        mma_gemm_async<<<grid, 256>>>(xr, nullptr, wa, proj1_b, h,
                                      n, 128, F1, 0, nullptr);
    }
    prep_zero<<<cdiv(2 * n, 256), 256>>>(deg, pool, cnt, wsum);
    hist_kernel<<<dim3(egrid, 2), 256>>>(ei0, ei1, deg);
    scan1_kernel<<<dim3(NB, 2), 256>>>(deg, rowptr, partials);
    scan2_kernel<<<2, 256>>>(partials);
    scan3_kernel<<<dim3(NB, 2), 256>>>(rowptr, partials, cursor);
    fillpos_kernel<<<dim3(egrid, 2), 256>>>(ei0, ei1, cursor, adj);
    round_copy<<<cdiv(128 * 128, 256), 256>>>(klin2_w, wc, 128 * 128);
    round_copy<<<cdiv(256 * 128, 256), 256>>>(proj2_w, wd, 256 * 128);

    // ---- Layer 1 (F=256, D=64) ----
    node_scores_kernel<<<cdiv(n * NHEAD, 256), 256>>>(
        h, as1_r0, ad1_r0, as1_r1, ad1_r1, s, d, n, F1, 64);
    agg_kernel<F1, 64><<<dim3(agg_blocks, 2), 256>>>(
        rowptr, deg, adj, h, s, d, o0, o1, n);
    {
        dim3 grid(F1 / GBN, cdiv(n, GBM), 2);
        mma_gemm_async<<<grid, 256>>>(o0, o1, wb, klin1_b, nullptr,
                                      n, F1, F1, 1, wsum);
    }
    semantic_kernel<<<1, 256>>>(wsum, q1, attn, F1, 1.f / n);

    // ---- Layer 2 (F=128, D=32) ----
    combine_kernel<<<cdiv((long)n * F1 / 4, 256), 256>>>(
        o0, o1, attn, comb, (long)n * F1 / 4);
    {
        dim3 grid(F2 / GBN, cdiv(n, GBM), 1);
        mma_gemm_async<<<grid, 256>>>(comb, nullptr, wd, proj2_b, h,
                                      n, F1, F2, 0, nullptr);
    }
    node_scores_kernel<<<cdiv(n * NHEAD, 256), 256>>>(
        h, as2_r0, ad2_r0, as2_r1, ad2_r1, s, d, n, F2, 32);
    agg_kernel<F2, 32><<<dim3(agg_blocks, 2), 256>>>(
        rowptr, deg, adj, h, s, d, o0, o1, n);
    {
        dim3 grid(F2 / GBN, cdiv(n, GBM), 2);
        mma_gemm_async<<<grid, 256>>>(o0, o1, wc, klin2_b, nullptr,
                                      n, F2, F2, 1, wsum + 2 * F1);
    }
    semantic_kernel<<<1, 256>>>(wsum + 2 * F1, q2, attn, F2, 1.f / n);

    // ---- Combine+pool+count (fused, run-length), head ----
    combine_pool_count<<<cdiv(n, 128), F2>>>(o0, o1, attn, batch, pool, cnt, n);
    head_kernel<<<NGRAPH, 64>>>(pool, cnt, d1_w, d1_b, bn_g, bn_b, bn_m, bn_v,
                                d2_w, d2_b, out);
}

// round 16
// speedup vs baseline: 1.0611x; 1.0192x over previous
#include <cuda_runtime.h>
#include <cuda_bf16.h>
#include <cstdint>
#include <math.h>

// Problem constants (match reference)
#define NNODES 50000
#define NEDGES 400000
#define NGRAPH 64
#define NHEAD  4
#define F1 256
#define F2 128
#define NB 196   // ceil(NNODES/256)

// ---------------------------------------------------------------------------
// Device scratch
// ---------------------------------------------------------------------------
__device__ float g_h[NNODES * F1];
__device__ float g_out0[NNODES * F1];
__device__ float g_out1[NNODES * F1];
__device__ float g_comb[NNODES * F1];       // combined layer-1 output (tf32)
__device__ float g_x[NNODES * 128];         // tf32-rounded input features
__device__ float g_wa[128 * 256];           // rounded proj1_w [K][F]
__device__ float g_wb[256 * 256];           // rounded klin1_w
__device__ float g_wc[128 * 128];           // rounded klin2_w
__device__ float g_wd[256 * 128];           // rounded proj2_w
__device__ float g_s[2 * NNODES * NHEAD];
__device__ float g_dd[2 * NNODES * NHEAD];
__device__ float g_wsum[2 * F1 + 2 * F2];   // layer1 @0, layer2 @512
__device__ float g_attn[2];
__device__ float g_pool[NGRAPH * F2];
__device__ float g_cnt[NGRAPH];
// CSR (by dst), 2 relations; adjacency stores SRC node ids directly
__device__ int g_deg[2 * NNODES];
__device__ int g_rowptr[2 * NNODES];
__device__ int g_cursor[2 * NNODES];
__device__ int g_adj[2 * NEDGES];
__device__ int g_partials[2 * NB];

// ---------------------------------------------------------------------------
// Helpers
// ---------------------------------------------------------------------------
__device__ __forceinline__ unsigned to_tf32_bits(float x) {
    unsigned r;
    asm("cvt.rna.tf32.f32 %0, %1;" : "=r"(r) : "f"(x));
    return r;
}
__device__ __forceinline__ float to_tf32(float x) {
    return __uint_as_float(to_tf32_bits(x));
}
__device__ __forceinline__ float tanh_fast(float x) {
    float y;
    asm("tanh.approx.f32 %0, %1;" : "=f"(y) : "f"(x));
    return y;
}

__device__ __forceinline__ void mma_tf32(float c[4],
                                         const unsigned a[4],
                                         const unsigned b[2]) {
    asm volatile(
        "mma.sync.aligned.m16n8k8.row.col.f32.tf32.tf32.f32 "
        "{%0,%1,%2,%3}, {%4,%5,%6,%7}, {%8,%9}, {%0,%1,%2,%3};"
        : "+f"(c[0]), "+f"(c[1]), "+f"(c[2]), "+f"(c[3])
        : "r"(a[0]), "r"(a[1]), "r"(a[2]), "r"(a[3]),
          "r"(b[0]), "r"(b[1]));
}

__device__ __forceinline__ void cp_async16(uint32_t s, const void* g, bool v) {
    int sz = v ? 16 : 0;
    asm volatile("cp.async.ca.shared.global [%0], [%1], 16, %2;"
                 :: "r"(s), "l"(g), "r"(sz));
}
__device__ __forceinline__ void cp_commit() {
    asm volatile("cp.async.commit_group;" ::: "memory");
}
template<int N>
__device__ __forceinline__ void cp_wait() {
    asm volatile("cp.async.wait_group %0;" :: "n"(N) : "memory");
}

__global__ void round_copy(const float* __restrict__ in,
                           float* __restrict__ out, long n) {
    long i = (long)blockIdx.x * blockDim.x + threadIdx.x;
    if (i < n) out[i] = to_tf32(in[i]);
}

// ---------------------------------------------------------------------------
// CSR build kernels
// ---------------------------------------------------------------------------
__global__ void prep_zero(int* __restrict__ deg, float* __restrict__ pool,
                          float* __restrict__ cnt, float* __restrict__ wsum) {
    int i = blockIdx.x * 256 + threadIdx.x;
    if (i < 2 * NNODES) deg[i] = 0;
    if (i < NGRAPH * F2) pool[i] = 0.f;
    if (i < NGRAPH) cnt[i] = 0.f;
    if (i < 2 * F1 + 2 * F2) wsum[i] = 0.f;
}

__global__ void hist_kernel(const int* __restrict__ ei0,
                            const int* __restrict__ ei1,
                            int* __restrict__ deg) {
    int r = blockIdx.y;
    const int* dst = (r == 0 ? ei0 : ei1) + NEDGES;
    int e = blockIdx.x * 256 + threadIdx.x;
    if (e < NEDGES) atomicAdd(&deg[r * NNODES + dst[e]], 1);
}

__global__ void scan1_kernel(const int* __restrict__ deg,
                             int* __restrict__ rowptr,
                             int* __restrict__ partials) {
    int r = blockIdx.y, b = blockIdx.x, t = threadIdx.x;
    int i = b * 256 + t;
    __shared__ int sh[256];
    int v = (i < NNODES) ? deg[r * NNODES + i] : 0;
    sh[t] = v;
    __syncthreads();
    for (int off = 1; off < 256; off <<= 1) {
        int x = (t >= off) ? sh[t - off] : 0;
        __syncthreads();
        sh[t] += x;
        __syncthreads();
    }
    if (i < NNODES) rowptr[r * NNODES + i] = sh[t] - v;  // exclusive
    if (t == 255) partials[r * NB + b] = sh[t];
}

__global__ void scan2_kernel(int* __restrict__ partials) {
    int r = blockIdx.x, t = threadIdx.x;
    __shared__ int sh[256];
    int v = (t < NB) ? partials[r * NB + t] : 0;
    sh[t] = v;
    __syncthreads();
    for (int off = 1; off < 256; off <<= 1) {
        int x = (t >= off) ? sh[t - off] : 0;
        __syncthreads();
        sh[t] += x;
        __syncthreads();
    }
    if (t < NB) partials[r * NB + t] = sh[t] - v;  // exclusive
}

__global__ void scan3_kernel(int* __restrict__ rowptr,
                             const int* __restrict__ partials,
                             int* __restrict__ cursor) {
    int r = blockIdx.y;
    int i = blockIdx.x * 256 + threadIdx.x;
    if (i < NNODES) {
        int v = rowptr[r * NNODES + i] + partials[r * NB + blockIdx.x];
        rowptr[r * NNODES + i] = v;
        cursor[r * NNODES + i] = v;
    }
}

__global__ void fillpos_kernel(const int* __restrict__ ei0,
                               const int* __restrict__ ei1,
                               int* __restrict__ cursor,
                               int* __restrict__ adj) {
    int r = blockIdx.y;
    const int* ei = (r == 0 ? ei0 : ei1);
    int e = blockIdx.x * 256 + threadIdx.x;
    if (e < NEDGES) {
        int pos = atomicAdd(&cursor[r * NNODES + ei[NEDGES + e]], 1);
        adj[r * NEDGES + pos] = ei[e];
    }
}

// ---------------------------------------------------------------------------
// Fast TF32 GEMM, cp.async 3-stage with 16-deep k-stages (two 8-col chunks
// per stage; per-chunk layouts identical to the proven conflict-free 8/132
// strides). Halves cp_wait+__syncthreads count vs 8-deep stages.
// DYNAMIC shared memory (49920 B > 48KB static limit):
//   As at float offset 0:      [3][2][128][8]   = 6144 floats
//   Bs at float offset 6144:   [3][2][8][132]   = 6336 floats
// k-pair slot remap: quad-thread tig supplies k = {2*tig, 2*tig+1} per chunk.
// A pre-rounded [M][K]; W pre-rounded [K][F]. C[M,F] = A @ W (+bias)
// mode 0: C = acc + bias; mode 1: colsum += sum_m tanh(acc + bias)
// grid.z selects A0/A1 (batched klin GEMMs); colsum offset = z*F.
// Requires K % 16 == 0 and K >= 32 (K in {128,256}).
// ---------------------------------------------------------------------------
#define GBM 128
#define GBN 128
#define FBK 16
#define FA_STRIDE 8
#define FB_STRIDE 132
#define FSTAGES 3
#define BS_FOFF (FSTAGES * 2 * GBM * FA_STRIDE)            // 6144 floats
#define GEMM_SMEM_BYTES ((BS_FOFF + FSTAGES * 2 * 8 * FB_STRIDE) * 4)  // 49920

__global__ __launch_bounds__(256) void mma_gemm_async(
    const float* __restrict__ A0, const float* __restrict__ A1,
    const float* __restrict__ W,
    const float* __restrict__ bias, float* __restrict__ C,
    int M, int K, int F, int mode, float* __restrict__ colsum)
{
    extern __shared__ float smem[];
    float* AsBase = smem;                 // [stage][ch][128][8]
    float* BsBase = smem + BS_FOFF;       // [stage][ch][8][132]

    const float* __restrict__ A = (blockIdx.z == 0) ? A0 : A1;
    float* cs = (mode == 1) ? colsum + blockIdx.z * F : nullptr;

    const int tid  = threadIdx.x;
    const int lane = tid & 31;
    const int warp = tid >> 5;
    const int wm   = warp & 1;
    const int wn   = warp >> 1;
    const int gid  = lane >> 2;
    const int tig  = lane & 3;
    const int k2   = tig * 2;

    const int rowBase = blockIdx.y * GBM;
    const int colBase = blockIdx.x * GBN;

    const int a_r = tid >> 1;          // 0..127
    const int a_c = (tid & 1) * 4;     // 0 or 4
    const int b_r = tid >> 5;          // 0..7
    const int b_c = (tid & 31) * 4;    // 0..124
    const bool a_valid = (rowBase + a_r) < M;
    const uint32_t a_sbase =
        (uint32_t)__cvta_generic_to_shared(&AsBase[a_r * FA_STRIDE + a_c]);
    const uint32_t b_sbase =
        (uint32_t)__cvta_generic_to_shared(&BsBase[b_r * FB_STRIDE + b_c]);
    const size_t a_goff = (size_t)(rowBase + a_r) * K + a_c;
    const size_t b_goff = (size_t)b_r * F + colBase + b_c;
    const uint32_t a_chunk_b = GBM * FA_STRIDE * 4;        // 4096
    const uint32_t b_chunk_b = 8 * FB_STRIDE * 4;          // 4224
    const uint32_t a_stage_b = 2 * a_chunk_b;
    const uint32_t b_stage_b = 2 * b_chunk_b;

    float acc[4][4][4];
#pragma unroll
    for (int mt = 0; mt < 4; mt++)
#pragma unroll
        for (int nt = 0; nt < 4; nt++)
#pragma unroll
            for (int i = 0; i < 4; i++) acc[mt][nt][i] = 0.f;

    const int KT = K / FBK;   // 8 or 16

#define ISSUE(stage, kt_) do {                                               \
        cp_async16(a_sbase + (stage) * a_stage_b,                            \
                   A + a_goff + (size_t)(kt_) * FBK, a_valid);               \
        cp_async16(a_sbase + (stage) * a_stage_b + a_chunk_b,                \
                   A + a_goff + (size_t)(kt_) * FBK + 8, a_valid);           \
        cp_async16(b_sbase + (stage) * b_stage_b,                            \
                   W + b_goff + (size_t)((kt_) * FBK) * F, true);            \
        cp_async16(b_sbase + (stage) * b_stage_b + b_chunk_b,                \
                   W + b_goff + (size_t)((kt_) * FBK + 8) * F, true);        \
        cp_commit();                                                         \
    } while (0)

    ISSUE(0, 0);
    ISSUE(1, 1);

    int stage = 0;
    for (int kt = 0; kt < KT; kt++) {
        const int rem = KT - kt - 1;
        if (rem >= 1) cp_wait<1>();
        else          cp_wait<0>();
        __syncthreads();

        const float* As = AsBase + stage * (2 * GBM * FA_STRIDE);
        const float* Bs = BsBase + stage * (2 * 8 * FB_STRIDE);
#pragma unroll
        for (int ch = 0; ch < 2; ch++) {
            const float* Ac = As + ch * (GBM * FA_STRIDE);
            const float* Bc = Bs + ch * (8 * FB_STRIDE);
            unsigned afr[4][4], bfr[4][2];
#pragma unroll
            for (int mt = 0; mt < 4; mt++) {
                int r = wm * 64 + mt * 16 + gid;
                float2 lo = *reinterpret_cast<const float2*>(&Ac[r * FA_STRIDE + k2]);
                float2 hi = *reinterpret_cast<const float2*>(&Ac[(r + 8) * FA_STRIDE + k2]);
                afr[mt][0] = __float_as_uint(lo.x);
                afr[mt][1] = __float_as_uint(hi.x);
                afr[mt][2] = __float_as_uint(lo.y);
                afr[mt][3] = __float_as_uint(hi.y);
            }
#pragma unroll
            for (int nt = 0; nt < 4; nt++) {
                int c = wn * 32 + nt * 8 + gid;
                bfr[nt][0] = __float_as_uint(Bc[k2 * FB_STRIDE + c]);
                bfr[nt][1] = __float_as_uint(Bc[(k2 + 1) * FB_STRIDE + c]);
            }
#pragma unroll
            for (int mt = 0; mt < 4; mt++)
#pragma unroll
                for (int nt = 0; nt < 4; nt++)
                    mma_tf32(acc[mt][nt], afr[mt], bfr[nt]);
        }

        if (kt + 2 < KT) {
            int ns = stage + 2; if (ns >= FSTAGES) ns -= FSTAGES;
            ISSUE(ns, kt + 2);
        }
        stage = (stage + 1 == FSTAGES) ? 0 : stage + 1;
    }
#undef ISSUE

    if (mode == 0) {
#pragma unroll
        for (int mt = 0; mt < 4; mt++) {
            int r0 = rowBase + wm * 64 + mt * 16 + gid;
            int r1 = r0 + 8;
#pragma unroll
            for (int nt = 0; nt < 4; nt++) {
                int gc = colBase + wn * 32 + nt * 8 + tig * 2;
                float b0 = bias[gc], b1 = bias[gc + 1];
                if (r0 < M) {
                    float2 v = make_float2(acc[mt][nt][0] + b0, acc[mt][nt][1] + b1);
                    *reinterpret_cast<float2*>(&C[(size_t)r0 * F + gc]) = v;
                }
                if (r1 < M) {
                    float2 v = make_float2(acc[mt][nt][2] + b0, acc[mt][nt][3] + b1);
                    *reinterpret_cast<float2*>(&C[(size_t)r1 * F + gc]) = v;
                }
            }
        }
    } else {
#pragma unroll
        for (int nt = 0; nt < 4; nt++) {
            int gc = colBase + wn * 32 + nt * 8 + tig * 2;
            float b0 = bias[gc], b1 = bias[gc + 1];
            float csA = 0.f, csB = 0.f;
#pragma unroll
            for (int mt = 0; mt < 4; mt++) {
                int r0 = rowBase + wm * 64 + mt * 16 + gid;
                int r1 = r0 + 8;
                if (r0 < M) {
                    csA += tanh_fast(acc[mt][nt][0] + b0);
                    csB += tanh_fast(acc[mt][nt][1] + b1);
                }
                if (r1 < M) {
                    csA += tanh_fast(acc[mt][nt][2] + b0);
                    csB += tanh_fast(acc[mt][nt][3] + b1);
                }
            }
            // reduce across gid (lanes with same tig share gc): xor 4,8,16
#pragma unroll
            for (int o = 4; o <= 16; o <<= 1) {
                csA += __shfl_xor_sync(0xffffffffu, csA, o);
                csB += __shfl_xor_sync(0xffffffffu, csB, o);
            }
            if (gid == 0) {
                atomicAdd(&cs[gc], csA);
                atomicAdd(&cs[gc + 1], csB);
            }
        }
    }
}

// ---------------------------------------------------------------------------
// Per-(node,head) attention scores, BOTH relations in one pass (h read once)
// ---------------------------------------------------------------------------
__global__ void node_scores_kernel(const float* __restrict__ h,
                                   const float* __restrict__ as0,
                                   const float* __restrict__ ad0,
                                   const float* __restrict__ as1,
                                   const float* __restrict__ ad1,
                                   float* __restrict__ s, float* __restrict__ d,
                                   int n, int F, int D)
{
    int idx = blockIdx.x * blockDim.x + threadIdx.x;
    if (idx >= n * NHEAD) return;
    int node = idx / NHEAD;
    int hh   = idx % NHEAD;
    const float4* hp4 = (const float4*)(h + (size_t)node * F + hh * D);
    const float4* a0 = (const float4*)(as0 + hh * D);
    const float4* b0 = (const float4*)(ad0 + hh * D);
    const float4* a1 = (const float4*)(as1 + hh * D);
    const float4* b1 = (const float4*)(ad1 + hh * D);
    float s0 = 0.f, d0 = 0.f, s1 = 0.f, d1 = 0.f;
    for (int i = 0; i < D / 4; i++) {
        float4 hv = hp4[i];
        float4 av = a0[i], bv = b0[i], cv = a1[i], dv = b1[i];
        s0 += hv.x * av.x + hv.y * av.y + hv.z * av.z + hv.w * av.w;
        d0 += hv.x * bv.x + hv.y * bv.y + hv.z * bv.z + hv.w * bv.w;
        s1 += hv.x * cv.x + hv.y * cv.y + hv.z * cv.z + hv.w * cv.w;
        d1 += hv.x * dv.x + hv.y * dv.y + hv.z * dv.z + hv.w * dv.w;
    }
    s[idx] = s0;               d[idx] = d0;
    s[n * NHEAD + idx] = s1;   d[n * NHEAD + idx] = d1;
}

// ---------------------------------------------------------------------------
// Gather-aggregate: warp per dst node, both relations (grid.y), float4 I/O.
// Pass 1 caches first-wave edge src + scores in regs; pass 2 shuffles them
// and processes TWO edges per iteration (sweet spot for deg~8).
// ---------------------------------------------------------------------------
template<int F, int D>
__global__ __launch_bounds__(256) void agg_kernel(
    const int* __restrict__ rowptr, const int* __restrict__ deg,
    const int* __restrict__ adjacency,
    const float* __restrict__ h, const float* __restrict__ s,
    const float* __restrict__ dvals,
    float* __restrict__ out0, float* __restrict__ out1, int n)
{
    const int r = blockIdx.y;
    float* __restrict__ out = r == 0 ? out0 : out1;
    const int* rp = rowptr + r * n;
    const int* dgp = deg + r * n;
    const int* __restrict__ adj = adjacency + r * NEDGES;
    const float4* __restrict__ sp4 =
        (const float4*)(s + (size_t)r * n * NHEAD);
    const float4* __restrict__ dp4 =
        (const float4*)(dvals + (size_t)r * n * NHEAD);

    int w = blockIdx.x * (blockDim.x >> 5) + (threadIdx.x >> 5);
    int lane = threadIdx.x & 31;
    if (w >= n) return;
    const int dg = dgp[w];
    const int st = rp[w];
    constexpr int C4 = F / 128;       // float4 per lane
    float4 acc4[C4];
#pragma unroll
    for (int c = 0; c < C4; c++) acc4[c] = make_float4(0.f, 0.f, 0.f, 0.f);
    float4 ddv = dp4[w];
    float dd[4] = {ddv.x, ddv.y, ddv.z, ddv.w};

    // pass 1: per-head max; cache first-wave (j = lane) src + scores
    int sr0 = 0;
    float vv[4] = {0.f, 0.f, 0.f, 0.f};
    float m[4] = {-1e30f, -1e30f, -1e30f, -1e30f};
    for (int j = lane; j < dg; j += 32) {
        int sr = adj[st + j];
        float4 sv = sp4[sr];
        float v[4];
        v[0] = sv.x + dd[0]; v[1] = sv.y + dd[1];
        v[2] = sv.z + dd[2]; v[3] = sv.w + dd[3];
#pragma unroll
        for (int t = 0; t < 4; t++) {
            v[t] = (v[t] >= 0.f) ? v[t] : 0.2f * v[t];
            m[t] = fmaxf(m[t], v[t]);
        }
        if (j == lane) {
            sr0 = sr;
#pragma unroll
            for (int t = 0; t < 4; t++) vv[t] = v[t];
        }
    }
#pragma unroll
    for (int o = 16; o > 0; o >>= 1)
#pragma unroll
        for (int t = 0; t < 4; t++)
            m[t] = fmaxf(m[t], __shfl_xor_sync(0xffffffffu, m[t], o));

    // pass 2: serial edges, 2 at a time; scores via shfl (j<32)
    float sums[4] = {0.f, 0.f, 0.f, 0.f};
    const int dg32 = dg < 32 ? dg : 32;
    int j = 0;
    for (; j + 1 < dg32; j += 2) {
        int srA = __shfl_sync(0xffffffffu, sr0, j);
        int srB = __shfl_sync(0xffffffffu, sr0, j + 1);
        float pA[4], pB[4];
#pragma unroll
        for (int t = 0; t < 4; t++) {
            float vA = __shfl_sync(0xffffffffu, vv[t], j);
            float vB = __shfl_sync(0xffffffffu, vv[t], j + 1);
            pA[t] = __expf(vA - m[t]);
            pB[t] = __expf(vB - m[t]);
            sums[t] += pA[t] + pB[t];
        }
        const float4* hA = (const float4*)(h + (size_t)srA * F);
        const float4* hB = (const float4*)(h + (size_t)srB * F);
#pragma unroll
        for (int c = 0; c < C4; c++) {
            int f0 = (lane + 32 * c) * 4;
            float4 hvA = hA[lane + 32 * c];
            float4 hvB = hB[lane + 32 * c];
            float pwA = pA[f0 / D], pwB = pB[f0 / D];
            acc4[c].x += hvA.x * pwA + hvB.x * pwB;
            acc4[c].y += hvA.y * pwA + hvB.y * pwB;
            acc4[c].z += hvA.z * pwA + hvB.z * pwB;
            acc4[c].w += hvA.w * pwA + hvB.w * pwB;
        }
    }
    if (j < dg32) {
        int sr = __shfl_sync(0xffffffffu, sr0, j);
        float p[4];
#pragma unroll
        for (int t = 0; t < 4; t++) {
            float v = __shfl_sync(0xffffffffu, vv[t], j);
            p[t] = __expf(v - m[t]);
            sums[t] += p[t];
        }
        const float4* hr4 = (const float4*)(h + (size_t)sr * F);
#pragma unroll
        for (int c = 0; c < C4; c++) {
            int f0 = (lane + 32 * c) * 4;
            float pw = p[f0 / D];
            float4 hv = hr4[lane + 32 * c];
            acc4[c].x += hv.x * pw; acc4[c].y += hv.y * pw;
            acc4[c].z += hv.z * pw; acc4[c].w += hv.w * pw;
        }
    }
    for (int jj = 32; jj < dg; jj++) {
        int sr = adj[st + jj];
        float4 sv = sp4[sr];
        float v[4];
        v[0] = sv.x + dd[0]; v[1] = sv.y + dd[1];
        v[2] = sv.z + dd[2]; v[3] = sv.w + dd[3];
        float p[4];
#pragma unroll
        for (int t = 0; t < 4; t++) {
            float x = (v[t] >= 0.f) ? v[t] : 0.2f * v[t];
            p[t] = __expf(x - m[t]);
            sums[t] += p[t];
        }
        const float4* hr4 = (const float4*)(h + (size_t)sr * F);
#pragma unroll
        for (int c = 0; c < C4; c++) {
            int f0 = (lane + 32 * c) * 4;
            float pw = p[f0 / D];
            float4 hv = hr4[lane + 32 * c];
            acc4[c].x += hv.x * pw; acc4[c].y += hv.y * pw;
            acc4[c].z += hv.z * pw; acc4[c].w += hv.w * pw;
        }
    }
    float4* out4 = (float4*)(out + (size_t)w * F);
#pragma unroll
    for (int c = 0; c < C4; c++) {
        int f0 = (lane + 32 * c) * 4;
        float inv = 1.f / (sums[f0 / D] + 1e-16f);
        float4 v;
        v.x = to_tf32(fmaxf(acc4[c].x * inv, 0.f));
        v.y = to_tf32(fmaxf(acc4[c].y * inv, 0.f));
        v.z = to_tf32(fmaxf(acc4[c].z * inv, 0.f));
        v.w = to_tf32(fmaxf(acc4[c].w * inv, 0.f));
        out4[lane + 32 * c] = v;
    }
}

// ---------------------------------------------------------------------------
// Semantic attention
// ---------------------------------------------------------------------------
__global__ void semantic_kernel(const float* __restrict__ wsum,
                                const float* __restrict__ q,
                                float* __restrict__ attn, int F, float invN)
{
    __shared__ float sh0[256], sh1[256];
    int t = threadIdx.x;
    float p0 = 0.f, p1 = 0.f;
    for (int f = t; f < F; f += 256) {
        float qf = q[f];
        p0 += wsum[f] * invN * qf;
        p1 += wsum[F + f] * invN * qf;
    }
    sh0[t] = p0; sh1[t] = p1;
    __syncthreads();
    for (int s = 128; s > 0; s >>= 1) {
        if (t < s) { sh0[t] += sh0[t + s]; sh1[t] += sh1[t + s]; }
        __syncthreads();
    }
    if (t == 0) {
        float m  = fmaxf(sh0[0], sh1[0]);
        float e0 = expf(sh0[0] - m);
        float e1 = expf(sh1[0] - m);
        float inv = 1.f / (e0 + e1);
        attn[0] = e0 * inv;
        attn[1] = e1 * inv;
    }
}

// ---------------------------------------------------------------------------
// Combine (inputs already relu'd): comb = tf32(at0*o0 + at1*o1), float4.
// ---------------------------------------------------------------------------
__global__ void combine_kernel(const float* __restrict__ o0,
                               const float* __restrict__ o1,
                               const float* __restrict__ attn,
                               float* __restrict__ comb, long n4)
{
    long i = (long)blockIdx.x * blockDim.x + threadIdx.x;
    if (i >= n4) return;
    float at0 = attn[0], at1 = attn[1];
    float4 a = ((const float4*)o0)[i];
    float4 b = ((const float4*)o1)[i];
    float4 v;
    v.x = to_tf32(at0 * a.x + at1 * b.x);
    v.y = to_tf32(at0 * a.y + at1 * b.y);
    v.z = to_tf32(at0 * a.z + at1 * b.z);
    v.w = to_tf32(at0 * a.w + at1 * b.w);
    ((float4*)comb)[i] = v;
}

// ---------------------------------------------------------------------------
// Final combine + pool + count, run-length batched (batch is sorted)
// ---------------------------------------------------------------------------
__global__ __launch_bounds__(F2) void combine_pool_count(
    const float* __restrict__ o0, const float* __restrict__ o1,
    const float* __restrict__ attn, const int* __restrict__ batch,
    float* __restrict__ pool, float* __restrict__ cnt, int n)
{
    int f = threadIdx.x;               // 0..127
    int base = blockIdx.x * 128;
    int end  = base + 128 < n ? base + 128 : n;
    if (base >= n) return;
    float at0 = attn[0], at1 = attn[1];
    float acc = 0.f;
    int cur = batch[base];
    int runstart = base;
    for (int i = base; i < end; i++) {
        int g = batch[i];
        if (g != cur) {
            atomicAdd(&pool[cur * F2 + f], acc);
            if (f == 0) atomicAdd(&cnt[cur], (float)(i - runstart));
            acc = 0.f; cur = g; runstart = i;
        }
        size_t off = (size_t)i * F2 + f;
        acc += at0 * o0[off] + at1 * o1[off];
    }
    atomicAdd(&pool[cur * F2 + f], acc);
    if (f == 0) atomicAdd(&cnt[cur], (float)(end - runstart));
}

__global__ void head_kernel(const float* __restrict__ pool,
                            const float* __restrict__ cnt,
                            const float* __restrict__ d1w,
                            const float* __restrict__ d1b,
                            const float* __restrict__ gma,
                            const float* __restrict__ bta,
                            const float* __restrict__ mean,
                            const float* __restrict__ var,
                            const float* __restrict__ d2w,
                            const float* __restrict__ d2b,
                            float* __restrict__ out)
{
    int g = blockIdx.x;
    int j = threadIdx.x;
    float c = fmaxf(cnt[g], 1.f);
    float inv = 1.f / c;
    float acc = d1b[j];
    for (int k = 0; k < F2; k++)
        acc += (pool[g * F2 + k] * inv) * d1w[k * 64 + j];
    acc = (acc - mean[j]) * rsqrtf(var[j] + 1e-5f) * gma[j] + bta[j];
    acc = (acc >= 0.f) ? acc : 0.1f * acc;
    float v = acc * d2w[j];
    __shared__ float red[64];
    red[j] = v;
    __syncthreads();
    for (int s = 32; s > 0; s >>= 1) {
        if (j < s) red[j] += red[j + s];
        __syncthreads();
    }
    if (j == 0) out[g] = red[0] + d2b[0];
}

// ---------------------------------------------------------------------------
// Host orchestration
// ---------------------------------------------------------------------------
static inline int cdiv(long a, int b) { return (int)((a + b - 1) / b); }

extern "C" void kernel_launch(void* const* d_in, const int* in_sizes, int n_in,
                              void* d_out, int out_size)
{
    const float* x       = (const float*)d_in[0];
    const int*   ei0     = (const int*)d_in[1];
    const int*   ei1     = (const int*)d_in[2];
    const int*   batch   = (const int*)d_in[3];
    const float* proj1_w = (const float*)d_in[4];
    const float* proj1_b = (const float*)d_in[5];
    const float* as1_r0  = (const float*)d_in[6];
    const float* ad1_r0  = (const float*)d_in[7];
    const float* as1_r1  = (const float*)d_in[8];
    const float* ad1_r1  = (const float*)d_in[9];
    const float* klin1_w = (const float*)d_in[10];
    const float* klin1_b = (const float*)d_in[11];
    const float* q1      = (const float*)d_in[12];
    const float* proj2_w = (const float*)d_in[13];
    const float* proj2_b = (const float*)d_in[14];
    const float* as2_r0  = (const float*)d_in[15];
    const float* ad2_r0  = (const float*)d_in[16];
    const float* as2_r1  = (const float*)d_in[17];
    const float* ad2_r1  = (const float*)d_in[18];
    const float* klin2_w = (const float*)d_in[19];
    const float* klin2_b = (const float*)d_in[20];
    const float* q2      = (const float*)d_in[21];
    const float* d1_w    = (const float*)d_in[22];
    const float* d1_b    = (const float*)d_in[23];
    const float* bn_g    = (const float*)d_in[24];
    const float* bn_b    = (const float*)d_in[25];
    const float* bn_m    = (const float*)d_in[26];
    const float* bn_v    = (const float*)d_in[27];
    const float* d2_w    = (const float*)d_in[28];
    const float* d2_b    = (const float*)d_in[29];
    float* out = (float*)d_out;

    float *h, *o0, *o1, *comb, *xr, *wa, *wb, *wc, *wd, *s, *d, *wsum, *attn,
          *pool, *cnt;
    int *deg, *rowptr, *cursor, *adj, *partials;
    cudaGetSymbolAddress((void**)&h,       g_h);
    cudaGetSymbolAddress((void**)&o0,      g_out0);
    cudaGetSymbolAddress((void**)&o1,      g_out1);
    cudaGetSymbolAddress((void**)&comb,    g_comb);
    cudaGetSymbolAddress((void**)&xr,      g_x);
    cudaGetSymbolAddress((void**)&wa,      g_wa);
    cudaGetSymbolAddress((void**)&wb,      g_wb);
    cudaGetSymbolAddress((void**)&wc,      g_wc);
    cudaGetSymbolAddress((void**)&wd,      g_wd);
    cudaGetSymbolAddress((void**)&s,       g_s);
    cudaGetSymbolAddress((void**)&d,       g_dd);
    cudaGetSymbolAddress((void**)&wsum,    g_wsum);
    cudaGetSymbolAddress((void**)&attn,    g_attn);
    cudaGetSymbolAddress((void**)&pool,    g_pool);
    cudaGetSymbolAddress((void**)&cnt,     g_cnt);
    cudaGetSymbolAddress((void**)&deg,     g_deg);
    cudaGetSymbolAddress((void**)&rowptr,  g_rowptr);
    cudaGetSymbolAddress((void**)&cursor,  g_cursor);
    cudaGetSymbolAddress((void**)&adj,     g_adj);
    cudaGetSymbolAddress((void**)&partials,g_partials);

    // allow 49920 B dynamic smem (idempotent; not an allocation / stream op)
    cudaFuncSetAttribute(mma_gemm_async,
                         cudaFuncAttributeMaxDynamicSharedMemorySize,
                         GEMM_SMEM_BYTES);

    const int n = NNODES, E = NEDGES;
    const int egrid = cdiv(E, 256);
    const int agg_blocks = cdiv(n, 8);

    // ---- launches 1-3: staging; launch #4 = proj1 GEMM (ncu capture) ----
    round_copy<<<cdiv((long)n * 128, 256), 256>>>(x, xr, (long)n * 128);      // 1
    round_copy<<<cdiv(128 * 256, 256), 256>>>(proj1_w, wa, 128 * 256);        // 2
    round_copy<<<cdiv(256 * 256, 256), 256>>>(klin1_w, wb, 256 * 256);        // 3
    {   // 4: proj1 GEMM (profile target)
        dim3 grid(F1 / GBN, cdiv(n, GBM), 1);
        mma_gemm_async<<<grid, 256, GEMM_SMEM_BYTES>>>(
            xr, nullptr, wa, proj1_b, h, n, 128, F1, 0, nullptr);
    }
    prep_zero<<<cdiv(2 * n, 256), 256>>>(deg, pool, cnt, wsum);
    hist_kernel<<<dim3(egrid, 2), 256>>>(ei0, ei1, deg);
    scan1_kernel<<<dim3(NB, 2), 256>>>(deg, rowptr, partials);
    scan2_kernel<<<2, 256>>>(partials);
    scan3_kernel<<<dim3(NB, 2), 256>>>(rowptr, partials, cursor);
    fillpos_kernel<<<dim3(egrid, 2), 256>>>(ei0, ei1, cursor, adj);
    round_copy<<<cdiv(128 * 128, 256), 256>>>(klin2_w, wc, 128 * 128);
    round_copy<<<cdiv(256 * 128, 256), 256>>>(proj2_w, wd, 256 * 128);

    // ---- Layer 1 (F=256, D=64) ----
    node_scores_kernel<<<cdiv(n * NHEAD, 256), 256>>>(
        h, as1_r0, ad1_r0, as1_r1, ad1_r1, s, d, n, F1, 64);
    agg_kernel<F1, 64><<<dim3(agg_blocks, 2), 256>>>(
        rowptr, deg, adj, h, s, d, o0, o1, n);
    {
        dim3 grid(F1 / GBN, cdiv(n, GBM), 2);
        mma_gemm_async<<<grid, 256, GEMM_SMEM_BYTES>>>(
            o0, o1, wb, klin1_b, nullptr, n, F1, F1, 1, wsum);
    }
    semantic_kernel<<<1, 256>>>(wsum, q1, attn, F1, 1.f / n);

    // ---- Layer 2 (F=128, D=32) ----
    combine_kernel<<<cdiv((long)n * F1 / 4, 256), 256>>>(
        o0, o1, attn, comb, (long)n * F1 / 4);
    {
        dim3 grid(F2 / GBN, cdiv(n, GBM), 1);
        mma_gemm_async<<<grid, 256, GEMM_SMEM_BYTES>>>(
            comb, nullptr, wd, proj2_b, h, n, F1, F2, 0, nullptr);
    }
    node_scores_kernel<<<cdiv(n * NHEAD, 256), 256>>>(
        h, as2_r0, ad2_r0, as2_r1, ad2_r1, s, d, n, F2, 32);
    agg_kernel<F2, 32><<<dim3(agg_blocks, 2), 256>>>(
        rowptr, deg, adj, h, s, d, o0, o1, n);
    {
        dim3 grid(F2 / GBN, cdiv(n, GBM), 2);
        mma_gemm_async<<<grid, 256, GEMM_SMEM_BYTES>>>(
            o0, o1, wc, klin2_b, nullptr, n, F2, F2, 1, wsum + 2 * F1);
    }
    semantic_kernel<<<1, 256>>>(wsum + 2 * F1, q2, attn, F2, 1.f / n);

    // ---- Combine+pool+count (fused, run-length), head ----
    combine_pool_count<<<cdiv(n, 128), F2>>>(o0, o1, attn, batch, pool, cnt, n);
    head_kernel<<<NGRAPH, 64>>>(pool, cnt, d1_w, d1_b, bn_g, bn_b, bn_m, bn_v,
                                d2_w, d2_b, out);
}